// round 2
// baseline (speedup 1.0000x reference)
#include <cuda_runtime.h>
#include <cstdint>
#include <cstddef>

// Problem constants
#define NAG  128   // agents
#define NNB  16    // neighbors
#define SEQ  64    // timesteps
#define DIM  128   // model dim
#define NH   4     // heads
#define DKH  32    // head dim
#define DFF  512

#define TPB  256
#define LDT  132   // padded stride for 64x128 smem tiles (bank-conflict-free)
#define LDA  66    // padded stride for 64x64 smem tiles

#define MASK_ELEMS ((size_t)NAG * NNB * SEQ * SEQ)   // 8388608

// Scratch (allocation-free: __device__ globals)
static __device__ float g_att_sum[(size_t)NAG * NH * SEQ * SEQ];            // 8 MB
static __device__ float g_res_inter[(size_t)NAG * NNB * SEQ * DIM];         // 64 MB
static __device__ int   g_mask_is_bytes;                                    // 1 = u8 storage

// ---------------------------------------------------------------------------
// Mask dtype detection: if the mask is stored as 1-byte bools, some 32-bit
// word of the buffer (random 0/1 bytes) will exceed 1. If stored as int32
// (values 0/1), every word in the first MASK_ELEMS/4 words is 0 or 1.
// ---------------------------------------------------------------------------
__global__ void detect_mask_kernel(const unsigned int* __restrict__ m) {
    const size_t nwords = MASK_ELEMS / 4;   // safe to read under both layouts
    int found = 0;
    for (size_t i = blockIdx.x * blockDim.x + threadIdx.x; i < nwords;
         i += (size_t)gridDim.x * blockDim.x)
        if (m[i] > 1u) { found = 1; break; }
    if (found) g_mask_is_bytes = 1;   // benign race: all writers store 1
}

// ---------------------------------------------------------------------------
// 64x128 output GEMM, 256 threads = 16 rowgroups x 16 colgroups,
// each thread computes a 4(row) x 8(col) tile. A in smem (padded lda),
// B row-major with runtime ldb (global weights or smem).
// ---------------------------------------------------------------------------
template <int K>
__device__ __forceinline__ void gemm_tile(const float* __restrict__ A, int lda,
                                          const float* __restrict__ B, int ldb,
                                          int rg, int cg, float acc[4][8]) {
    const int r0 = rg * 4, c0 = cg * 8;
    const float* Ar = A + r0 * lda;
    const float* Bp = B + c0;
#pragma unroll 4
    for (int k = 0; k < K; ++k) {
        float a0 = Ar[k];
        float a1 = Ar[lda + k];
        float a2 = Ar[2 * lda + k];
        float a3 = Ar[3 * lda + k];
        float4 b0 = *(const float4*)(Bp);
        float4 b1 = *(const float4*)(Bp + 4);
        Bp += ldb;
        float bb[8] = {b0.x, b0.y, b0.z, b0.w, b1.x, b1.y, b1.z, b1.w};
#pragma unroll
        for (int j = 0; j < 8; ++j) {
            acc[0][j] = fmaf(a0, bb[j], acc[0][j]);
            acc[1][j] = fmaf(a1, bb[j], acc[1][j]);
            acc[2][j] = fmaf(a2, bb[j], acc[2][j]);
            acc[3][j] = fmaf(a3, bb[j], acc[3][j]);
        }
    }
}

__device__ __forceinline__ void store_tile(float acc[4][8], float* dst, int rg, int cg) {
#pragma unroll
    for (int i = 0; i < 4; ++i)
#pragma unroll
        for (int j = 0; j < 8; ++j)
            dst[(rg * 4 + i) * LDT + cg * 8 + j] = acc[i][j];
}

// Load a 64x128 row-major global tile into padded smem (stride LDT).
__device__ __forceinline__ void load_tile(const float* __restrict__ src, float* dst) {
    for (int i = threadIdx.x; i < 64 * 32; i += TPB) {
        int row = i >> 5, c4 = i & 31;
        *(float4*)(dst + row * LDT + c4 * 4) = *(const float4*)(src + row * 128 + c4 * 4);
    }
}

// LayerNorm over rows of a 64x128 smem buffer (stride ld), write to global
// row-major [64,128]. 4 threads per row, quad shuffle reductions.
__device__ __forceinline__ void layernorm_store(const float* __restrict__ buf, int ld,
                                                const float* __restrict__ gam,
                                                const float* __restrict__ bet,
                                                float* __restrict__ out) {
    const int s = threadIdx.x >> 2, q = threadIdx.x & 3;
    const float* row = buf + s * ld;
    float sum = 0.f;
#pragma unroll
    for (int j = 0; j < 32; ++j) sum += row[q * 32 + j];
    sum += __shfl_xor_sync(0xffffffffu, sum, 1);
    sum += __shfl_xor_sync(0xffffffffu, sum, 2);
    float mean = sum * (1.f / 128.f);
    float vs = 0.f;
#pragma unroll
    for (int j = 0; j < 32; ++j) { float d = row[q * 32 + j] - mean; vs = fmaf(d, d, vs); }
    vs += __shfl_xor_sync(0xffffffffu, vs, 1);
    vs += __shfl_xor_sync(0xffffffffu, vs, 2);
    float rstd = rsqrtf(vs * (1.f / 128.f) + 1e-5f);
#pragma unroll
    for (int j = 0; j < 32; ++j) {
        int c = q * 32 + j;
        out[s * 128 + c] = (row[c] - mean) * rstd * gam[c] + bet[c];
    }
}

// FFN (relu(x@W1)@W2 + x), then LN, then store. x_s/h_s are 64x128 smem
// tiles (stride LDT). W1: (128,512), W2: (512,128). Processes DFF in 4 chunks.
__device__ __forceinline__ void ffn_ln_store(const float* __restrict__ x_s,
                                             float* __restrict__ h_s,
                                             const float* __restrict__ W1,
                                             const float* __restrict__ W2,
                                             const float* __restrict__ gam,
                                             const float* __restrict__ bet,
                                             float* __restrict__ out,
                                             int rg, int cg) {
    float o[4][8] = {};
#pragma unroll 1
    for (int ch = 0; ch < 4; ++ch) {
        float ha[4][8] = {};
        gemm_tile<128>(x_s, LDT, W1 + ch * 128, DFF, rg, cg, ha);
#pragma unroll
        for (int i = 0; i < 4; ++i)
#pragma unroll
            for (int j = 0; j < 8; ++j)
                h_s[(rg * 4 + i) * LDT + cg * 8 + j] = fmaxf(ha[i][j], 0.f);
        __syncthreads();
        gemm_tile<128>(h_s, LDT, W2 + (size_t)ch * 128 * 128, 128, rg, cg, o);
        __syncthreads();
    }
#pragma unroll
    for (int i = 0; i < 4; ++i)
#pragma unroll
        for (int j = 0; j < 8; ++j) {
            int idx = (rg * 4 + i) * LDT + cg * 8 + j;
            h_s[idx] = o[i][j] + x_s[idx];
        }
    __syncthreads();
    layernorm_store(h_s, LDT, gam, bet, out);
}

// ---------------------------------------------------------------------------
// Kernel A: per-(agent,neighbor) MHA. QKV proj -> masked softmax attention
// (accumulating att_i sums via atomics) -> @V -> @W_fc + residual -> LN.
// ---------------------------------------------------------------------------
__global__ void __launch_bounds__(TPB) kernel_mha(
    const float* __restrict__ nbemb, const void* __restrict__ mask,
    const float* __restrict__ WQ, const float* __restrict__ WK,
    const float* __restrict__ WV, const float* __restrict__ Wfc,
    const float* __restrict__ lng, const float* __restrict__ lnb) {
    extern __shared__ float sm[];
    float* emb_s = sm;                  // 64*LDT
    float* q_s   = sm + 8448;
    float* k_s   = sm + 2 * 8448;
    float* v_s   = sm + 3 * 8448;
    float* res_s = sm + 4 * 8448;
    float* sc_s  = sm + 5 * 8448;       // 64*LDA
    const int b = blockIdx.x;           // n*16 + nn
    const int tid = threadIdx.x;
    const int rg = tid >> 4, cg = tid & 15;
    const int mask_bytes = g_mask_is_bytes;   // uniform

    load_tile(nbemb + (size_t)b * SEQ * DIM, emb_s);
    __syncthreads();

    // QKV projections
    {
        float acc[4][8] = {};
        gemm_tile<128>(emb_s, LDT, WQ, 128, rg, cg, acc);
        store_tile(acc, q_s, rg, cg);
    }
    {
        float acc[4][8] = {};
        gemm_tile<128>(emb_s, LDT, WK, 128, rg, cg, acc);
        store_tile(acc, k_s, rg, cg);
    }
    {
        float acc[4][8] = {};
        gemm_tile<128>(emb_s, LDT, WV, 128, rg, cg, acc);
        store_tile(acc, v_s, rg, cg);
    }
    __syncthreads();

    const int s = tid >> 2, q4 = tid & 3;
    const float iscale = 0.17677669529663687f;  // 1/sqrt(32)
    const int n = b >> 4;

    // Preload this thread's 16 mask bits (dtype-robust), reused for all heads.
    bool mk16[16];
    {
        const size_t base = ((size_t)b * SEQ + s) * SEQ;
        if (mask_bytes) {
            const unsigned char* mp = (const unsigned char*)mask + base;
#pragma unroll
            for (int j = 0; j < 16; ++j) mk16[j] = mp[j * 4 + q4] != 0;
        } else {
            const int* mp = (const int*)mask + base;
#pragma unroll
            for (int j = 0; j < 16; ++j) mk16[j] = mp[j * 4 + q4] != 0;
        }
    }

#pragma unroll 1
    for (int h = 0; h < NH; ++h) {
        // scores row s (this thread owns t = j*4 + q4)
        float qreg[32];
        const float* qrow = q_s + s * LDT + h * 32;
#pragma unroll
        for (int kk = 0; kk < 32; ++kk) qreg[kk] = qrow[kk];
        float val[16];
#pragma unroll
        for (int j = 0; j < 16; ++j) {
            int t = j * 4 + q4;
            const float* krow = k_s + t * LDT + h * 32;
            float a = 0.f;
#pragma unroll
            for (int kk = 0; kk < 32; ++kk) a = fmaf(qreg[kk], krow[kk], a);
            val[j] = mk16[j] ? a * iscale : -1e9f;
        }
        // softmax over t (quad cooperates on a row)
        float mx = val[0];
#pragma unroll
        for (int j = 1; j < 16; ++j) mx = fmaxf(mx, val[j]);
        mx = fmaxf(mx, __shfl_xor_sync(0xffffffffu, mx, 1));
        mx = fmaxf(mx, __shfl_xor_sync(0xffffffffu, mx, 2));
        float ssum = 0.f;
#pragma unroll
        for (int j = 0; j < 16; ++j) { val[j] = expf(val[j] - mx); ssum += val[j]; }
        ssum += __shfl_xor_sync(0xffffffffu, ssum, 1);
        ssum += __shfl_xor_sync(0xffffffffu, ssum, 2);
        float inv = 1.f / ssum;
        float* arow = g_att_sum + (((size_t)n * NH + h) * SEQ + s) * SEQ;
#pragma unroll
        for (int j = 0; j < 16; ++j) {
            int t = j * 4 + q4;
            float p = val[j] * inv;
            sc_s[s * LDA + t] = p;
            atomicAdd(arow + t, p);
        }
        __syncwarp();
        // P @ V_h : this thread owns (row s, 8 cols of the 32-col head slice)
        float oacc[8] = {};
        const float* prow = sc_s + s * LDA;
        const float* vbase = v_s + h * 32 + q4 * 8;
#pragma unroll 4
        for (int t = 0; t < 64; ++t) {
            float p = prow[t];
            const float* vr = vbase + t * LDT;
#pragma unroll
            for (int j = 0; j < 8; ++j) oacc[j] = fmaf(p, vr[j], oacc[j]);
        }
        float* rdst = res_s + s * LDT + h * 32 + q4 * 8;
#pragma unroll
        for (int j = 0; j < 8; ++j) rdst[j] = oacc[j];
        __syncwarp();
    }
    __syncthreads();

    // res @ W_fc + emb, then LN -> res_inter
    {
        float acc[4][8] = {};
        gemm_tile<128>(res_s, LDT, Wfc, 128, rg, cg, acc);
#pragma unroll
        for (int i = 0; i < 4; ++i)
#pragma unroll
            for (int j = 0; j < 8; ++j) {
                int idx = (rg * 4 + i) * LDT + cg * 8 + j;
                q_s[idx] = acc[i][j] + emb_s[idx];
            }
    }
    __syncthreads();
    layernorm_store(q_s, LDT, lng, lnb, g_res_inter + (size_t)b * SEQ * DIM);
}

// ---------------------------------------------------------------------------
// Kernel B: per-agent self path. att_self + f*mean(att_i), per-head
// (att @ x) @ W_SI accumulation, FFN + LN -> x output.
// ---------------------------------------------------------------------------
__global__ void __launch_bounds__(TPB) kernel_self(
    const float* __restrict__ xemb, const float* __restrict__ af,
    const float* __restrict__ WSI, const float* __restrict__ W1,
    const float* __restrict__ W2, const float* __restrict__ gam,
    const float* __restrict__ bet, float* __restrict__ out) {
    extern __shared__ float sm[];
    float* x_s  = sm;                 // 64*LDT
    float* t_s  = sm + 8448;
    float* x1_s = sm + 2 * 8448;
    float* h_s  = sm + 3 * 8448;
    float* a_h  = sm + 4 * 8448;      // 64*LDA
    const int nAg = blockIdx.x;
    const int tid = threadIdx.x;
    const int rg = tid >> 4, cg = tid & 15;
    const int s = tid >> 2, q4 = tid & 3;

    load_tile(xemb + (size_t)nAg * SEQ * DIM, x_s);
    __syncthreads();

    // self scores: x_s @ x_s^T / sqrt(128), softmax -> held in registers
    float val[16] = {};
#pragma unroll 1
    for (int kc = 0; kc < 4; ++kc) {
        float qreg[32];
        const float* qrow = x_s + s * LDT + kc * 32;
#pragma unroll
        for (int kk = 0; kk < 32; ++kk) qreg[kk] = qrow[kk];
#pragma unroll
        for (int j = 0; j < 16; ++j) {
            int t = j * 4 + q4;
            const float* kr = x_s + t * LDT + kc * 32;
            float a = val[j];
#pragma unroll
            for (int kk = 0; kk < 32; ++kk) a = fmaf(qreg[kk], kr[kk], a);
            val[j] = a;
        }
    }
    const float isd = 0.08838834764831845f;  // 1/sqrt(128)
    float mx = val[0] * isd;
#pragma unroll
    for (int j = 0; j < 16; ++j) { val[j] *= isd; mx = fmaxf(mx, val[j]); }
    mx = fmaxf(mx, __shfl_xor_sync(0xffffffffu, mx, 1));
    mx = fmaxf(mx, __shfl_xor_sync(0xffffffffu, mx, 2));
    float ssum = 0.f;
#pragma unroll
    for (int j = 0; j < 16; ++j) { val[j] = expf(val[j] - mx); ssum += val[j]; }
    ssum += __shfl_xor_sync(0xffffffffu, ssum, 1);
    ssum += __shfl_xor_sync(0xffffffffu, ssum, 2);
    float inv = 1.f / ssum;
#pragma unroll
    for (int j = 0; j < 16; ++j) val[j] *= inv;   // att_self[s][t]

    const float fct = af[0] * (1.f / NNB);
    float accx[4][8] = {};
#pragma unroll 1
    for (int h = 0; h < NH; ++h) {
        const float* arow = g_att_sum + (((size_t)nAg * NH + h) * SEQ + s) * SEQ;
#pragma unroll
        for (int j = 0; j < 16; ++j) {
            int t = j * 4 + q4;
            a_h[s * LDA + t] = val[j] + fct * arow[t];
        }
        __syncthreads();
        float ta[4][8] = {};
        gemm_tile<64>(a_h, LDA, x_s, LDT, rg, cg, ta);     // att_h @ x  -> (64,128)
        store_tile(ta, t_s, rg, cg);
        __syncthreads();
        gemm_tile<128>(t_s, LDT, WSI + (size_t)h * 128 * 128, 128, rg, cg, accx);
        __syncthreads();
    }
    store_tile(accx, x1_s, rg, cg);
    __syncthreads();
    ffn_ln_store(x1_s, h_s, W1, W2, gam, bet, out + (size_t)nAg * SEQ * DIM, rg, cg);
}

// ---------------------------------------------------------------------------
// Kernel C: per-(agent,neighbor) FFN + LN on res_inter -> nb output.
// ---------------------------------------------------------------------------
__global__ void __launch_bounds__(TPB) kernel_nb_ffn(
    const float* __restrict__ W1, const float* __restrict__ W2,
    const float* __restrict__ gam, const float* __restrict__ bet,
    float* __restrict__ out) {
    extern __shared__ float sm[];
    float* x_s = sm;
    float* h_s = sm + 8448;
    const int b = blockIdx.x;
    const int tid = threadIdx.x;
    load_tile(g_res_inter + (size_t)b * SEQ * DIM, x_s);
    __syncthreads();
    ffn_ln_store(x_s, h_s, W1, W2, gam, bet, out + (size_t)b * SEQ * DIM,
                 tid >> 4, tid & 15);
}

// ---------------------------------------------------------------------------
extern "C" void kernel_launch(void* const* d_in, const int* in_sizes, int n_in,
                              void* d_out, int out_size) {
    const float* x_emb  = (const float*)d_in[0];
    const float* nb_emb = (const float*)d_in[1];
    const void*  mask   = d_in[2];
    const float* att_f  = (const float*)d_in[3];
    const float* WQ     = (const float*)d_in[4];
    const float* WK     = (const float*)d_in[5];
    const float* WV     = (const float*)d_in[6];
    const float* Wfc    = (const float*)d_in[7];
    const float* ln_mg  = (const float*)d_in[8];
    const float* ln_mb  = (const float*)d_in[9];
    const float* WSI    = (const float*)d_in[10];
    const float* W1s    = (const float*)d_in[11];
    const float* W2s    = (const float*)d_in[12];
    const float* ln_sg  = (const float*)d_in[13];
    const float* ln_sb  = (const float*)d_in[14];
    const float* W1i    = (const float*)d_in[15];
    const float* W2i    = (const float*)d_in[16];
    const float* ln_ig  = (const float*)d_in[17];
    const float* ln_ib  = (const float*)d_in[18];
    float* out_x  = (float*)d_out;
    float* out_nb = out_x + (size_t)NAG * SEQ * DIM;

    void* att_ptr = nullptr;
    cudaGetSymbolAddress(&att_ptr, g_att_sum);
    cudaMemsetAsync(att_ptr, 0, sizeof(float) * (size_t)NAG * NH * SEQ * SEQ, 0);
    void* flag_ptr = nullptr;
    cudaGetSymbolAddress(&flag_ptr, g_mask_is_bytes);
    cudaMemsetAsync(flag_ptr, 0, sizeof(int), 0);
    detect_mask_kernel<<<256, 256>>>((const unsigned int*)mask);

    const size_t smA = sizeof(float) * (5 * 8448 + 64 * LDA);   // ~185.9 KB
    const size_t smB = sizeof(float) * (4 * 8448 + 64 * LDA);   // ~152.1 KB
    const size_t smC = sizeof(float) * (2 * 8448);              // ~67.6 KB
    cudaFuncSetAttribute(kernel_mha,    cudaFuncAttributeMaxDynamicSharedMemorySize, (int)smA);
    cudaFuncSetAttribute(kernel_self,   cudaFuncAttributeMaxDynamicSharedMemorySize, (int)smB);
    cudaFuncSetAttribute(kernel_nb_ffn, cudaFuncAttributeMaxDynamicSharedMemorySize, (int)smC);

    kernel_mha<<<NAG * NNB, TPB, smA>>>(nb_emb, mask, WQ, WK, WV, Wfc, ln_mg, ln_mb);
    kernel_self<<<NAG, TPB, smB>>>(x_emb, att_f, WSI, W1s, W2s, ln_sg, ln_sb, out_x);
    kernel_nb_ffn<<<NAG * NNB, TPB, smC>>>(W1i, W2i, ln_ig, ln_ib, out_nb);
}

// round 5
// speedup vs baseline: 2.9060x; 2.9060x over previous
#include <cuda_runtime.h>
#include <cuda_bf16.h>
#include <cstdint>
#include <cstddef>

// Problem constants
#define NAG  128
#define NNB  16
#define SEQ  64
#define DIM  128
#define NH   4
#define DFF  512

#define TPB  256
#define LDT  132    // fp32 padded stride (64/128 x 128 tiles)
#define LDA  66     // fp32 padded stride (64x64 score tiles)
#define LDB  136    // bf16 padded stride (ldmatrix conflict-free: 272B rows)
#define LDX  132
#define IMG  (128 * LDB)

#define MASK_ELEMS ((size_t)NAG * NNB * SEQ * SEQ)

// Scratch (allocation-free: __device__ globals)
static __device__ float g_att_sum[(size_t)NAG * NH * SEQ * SEQ];
static __device__ float g_res_inter[(size_t)NAG * NNB * SEQ * DIM];
static __device__ int   g_mask_is_bytes;
// 12 pre-transposed bf16 weight images [n][k], padded stride LDB:
// 0..2: WQ^T, WK^T, WV^T   3: Wfc^T   4+c: W1i^T chunk c   8+c: W2i^T chunk c
static __device__ __nv_bfloat16 g_wimg[12 * IMG];

// ===========================================================================
// mma.sync / ldmatrix helpers (sm_80 baseline features -> valid compute_103)
// ===========================================================================
__device__ __forceinline__ uint32_t smem_u32(const void* p) {
    uint32_t a;
    asm("{ .reg .u64 t; cvta.to.shared.u64 t, %1; cvt.u32.u64 %0, t; }" : "=r"(a) : "l"(p));
    return a;
}

struct Frag4 { uint32_t x[4]; };

__device__ __forceinline__ Frag4 ldsm4(uint32_t addr) {
    Frag4 f;
    asm volatile("ldmatrix.sync.aligned.m8n8.x4.shared.b16 {%0,%1,%2,%3}, [%4];"
                 : "=r"(f.x[0]), "=r"(f.x[1]), "=r"(f.x[2]), "=r"(f.x[3]) : "r"(addr));
    return f;
}

__device__ __forceinline__ void mma16816(float c[4], const Frag4& a, uint32_t b0, uint32_t b1) {
    asm volatile("mma.sync.aligned.m16n8k16.row.col.f32.bf16.bf16.f32 "
                 "{%0,%1,%2,%3}, {%4,%5,%6,%7}, {%8,%9}, {%0,%1,%2,%3};"
                 : "+f"(c[0]), "+f"(c[1]), "+f"(c[2]), "+f"(c[3])
                 : "r"(a.x[0]), "r"(a.x[1]), "r"(a.x[2]), "r"(a.x[3]), "r"(b0), "r"(b1));
}

// Warp GEMM: out tile MT*16 x 64 at (mrow, ncol). A: [M][LDB] bf16 smem row-major.
// B: [N][LDB] bf16 smem = B^T row-major (N x K). K = 128 fixed.
template <int MT>
__device__ __forceinline__ void wgemm64(uint32_t aBase, int mrow, uint32_t bBase, int ncol,
                                        float (*acc)[8][4]) {
    const int lane = threadIdx.x & 31;
    const int lr = lane & 15, lc = (lane >> 4) * 8;
    const uint32_t aAddr = aBase + (uint32_t)((mrow + lr) * LDB + lc) * 2;
    const uint32_t bAddr = bBase + (uint32_t)((ncol + lr) * LDB + lc) * 2;
#pragma unroll
    for (int k = 0; k < 128; k += 16) {
        Frag4 af[MT];
#pragma unroll
        for (int mt = 0; mt < MT; ++mt)
            af[mt] = ldsm4(aAddr + (uint32_t)(mt * 16 * LDB + k) * 2);
#pragma unroll
        for (int bt = 0; bt < 4; ++bt) {
            Frag4 bf = ldsm4(bAddr + (uint32_t)(bt * 16 * LDB + k) * 2);
#pragma unroll
            for (int mt = 0; mt < MT; ++mt) {
                mma16816(acc[mt][2 * bt],     af[mt], bf.x[0], bf.x[2]);
                mma16816(acc[mt][2 * bt + 1], af[mt], bf.x[1], bf.x[3]);
            }
        }
    }
}

// ===========================================================================
// Mask dtype detection
// ===========================================================================
__global__ void detect_mask_kernel(const unsigned int* __restrict__ m) {
    const size_t nwords = MASK_ELEMS / 4;
    int found = 0;
    for (size_t i = blockIdx.x * blockDim.x + threadIdx.x; i < nwords;
         i += (size_t)gridDim.x * blockDim.x)
        if (m[i] > 1u) { found = 1; break; }
    if (found) g_mask_is_bytes = 1;
}

// ===========================================================================
// Prep: 12 transposed bf16 weight images, padded stride LDB
// ===========================================================================
__global__ void prep_weights_kernel(const float* __restrict__ WQ, const float* __restrict__ WK,
                                    const float* __restrict__ WV, const float* __restrict__ Wfc,
                                    const float* __restrict__ W1i, const float* __restrict__ W2i) {
    const int total = 12 * 128 * 32;   // one uint2 (4 bf16) per thread-iter
    for (int idx = blockIdx.x * blockDim.x + threadIdx.x; idx < total;
         idx += gridDim.x * blockDim.x) {
        int img = idx / (128 * 32);
        int rem = idx - img * (128 * 32);
        int n = rem >> 5;
        int k0 = (rem & 31) * 4;
        float v[4];
        if (img < 4) {
            const float* W = (img == 0) ? WQ : (img == 1) ? WK : (img == 2) ? WV : Wfc;
#pragma unroll
            for (int t = 0; t < 4; ++t) v[t] = W[(k0 + t) * 128 + n];
        } else if (img < 8) {
            int c = img - 4;
#pragma unroll
            for (int t = 0; t < 4; ++t) v[t] = W1i[(k0 + t) * DFF + c * 128 + n];
        } else {
            int c = img - 8;
#pragma unroll
            for (int t = 0; t < 4; ++t) v[t] = W2i[(c * 128 + k0 + t) * DIM + n];
        }
        __nv_bfloat16 b4[4];
#pragma unroll
        for (int t = 0; t < 4; ++t) b4[t] = __float2bfloat16(v[t]);
        *(uint2*)(g_wimg + (size_t)img * IMG + n * LDB + k0) = *(uint2*)b4;
    }
}

// ===========================================================================
// Kernel A: per-(agent,neighbor) MHA. QKV + fc via HMMA; attention scalar fp32.
// smem: emb_s | q_s | k_s | v_s | res_s (fp32 64xLDT each) | U (17408B) | wb (34816B)
// ===========================================================================
#define A_U   168960
#define A_WB  186368
#define A_TOT 221184

__global__ void __launch_bounds__(TPB) kernel_mha(
    const float* __restrict__ nbemb, const void* __restrict__ mask,
    const float* __restrict__ lng, const float* __restrict__ lnb) {
    extern __shared__ char smraw[];
    float* emb_s = (float*)smraw;
    float* q_s   = (float*)(smraw + 33792);
    float* k_s   = (float*)(smraw + 67584);
    float* v_s   = (float*)(smraw + 101376);
    float* res_s = (float*)(smraw + 135168);
    float* sc_s  = (float*)(smraw + A_U);               // aliases ubf (phased)
    __nv_bfloat16* ubf = (__nv_bfloat16*)(smraw + A_U); // A-operand image (64xLDB)
    __nv_bfloat16* wb  = (__nv_bfloat16*)(smraw + A_WB);

    const int b = blockIdx.x;
    const int tid = threadIdx.x;
    const int w = tid >> 5, lane = tid & 31;
    const int g = lane >> 2, t2 = (lane & 3) * 2;
    const int wrA = w & 3, wcA = w >> 2;     // 4 x 2 warp grid over 64x128
    const int mask_bytes = g_mask_is_bytes;
    const uint32_t ubfAddr = smem_u32(ubf);
    const uint32_t wbAddr  = smem_u32(wb);

    // load emb: fp32 padded + bf16 image
    const float* src = nbemb + (size_t)b * SEQ * DIM;
    for (int i = tid; i < 64 * 32; i += TPB) {
        int r = i >> 5, c4 = (i & 31) * 4;
        float4 v = *(const float4*)(src + r * DIM + c4);
        *(float4*)(emb_s + r * LDT + c4) = v;
        *(__nv_bfloat162*)(ubf + r * LDB + c4)     = __floats2bfloat162_rn(v.x, v.y);
        *(__nv_bfloat162*)(ubf + r * LDB + c4 + 2) = __floats2bfloat162_rn(v.z, v.w);
    }
    __syncthreads();

    // QKV projections via HMMA
    {
        float* dsts[3] = {q_s, k_s, v_s};
#pragma unroll 1
        for (int wi = 0; wi < 3; ++wi) {
            const uint4* ws = (const uint4*)(g_wimg + (size_t)wi * IMG);
            uint4* wd = (uint4*)wb;
            for (int i = tid; i < 2176; i += TPB) wd[i] = ws[i];
            __syncthreads();
            float acc[1][8][4] = {};
            wgemm64<1>(ubfAddr, wrA * 16, wbAddr, wcA * 64, acc);
            float* dq = dsts[wi];
            const int r0 = wrA * 16 + g;
#pragma unroll
            for (int nt = 0; nt < 8; ++nt) {
                int col = wcA * 64 + nt * 8 + t2;
                *(float2*)(dq + r0 * LDT + col)       = make_float2(acc[0][nt][0], acc[0][nt][1]);
                *(float2*)(dq + (r0 + 8) * LDT + col) = make_float2(acc[0][nt][2], acc[0][nt][3]);
            }
            __syncthreads();
        }
    }

    // attention (scalar fp32) — ubf dead, U now = sc_s
    const int s = tid >> 2, q4 = tid & 3;
    const float iscale = 0.17677669529663687f;
    const int n = b >> 4;

    bool mk16[16];
    {
        const size_t base = ((size_t)b * SEQ + s) * SEQ;
        if (mask_bytes) {
            const unsigned char* mp = (const unsigned char*)mask + base;
#pragma unroll
            for (int j = 0; j < 16; ++j) mk16[j] = mp[j * 4 + q4] != 0;
        } else {
            const int* mp = (const int*)mask + base;
#pragma unroll
            for (int j = 0; j < 16; ++j) mk16[j] = mp[j * 4 + q4] != 0;
        }
    }

#pragma unroll 1
    for (int h = 0; h < NH; ++h) {
        float qreg[32];
        const float* qrow = q_s + s * LDT + h * 32;
#pragma unroll
        for (int kk = 0; kk < 32; ++kk) qreg[kk] = qrow[kk];
        float val[16];
#pragma unroll
        for (int j = 0; j < 16; ++j) {
            int t = j * 4 + q4;
            const float* krow = k_s + t * LDT + h * 32;
            float a = 0.f;
#pragma unroll
            for (int kk = 0; kk < 32; ++kk) a = fmaf(qreg[kk], krow[kk], a);
            val[j] = mk16[j] ? a * iscale : -1e9f;
        }
        float mx = val[0];
#pragma unroll
        for (int j = 1; j < 16; ++j) mx = fmaxf(mx, val[j]);
        mx = fmaxf(mx, __shfl_xor_sync(0xffffffffu, mx, 1));
        mx = fmaxf(mx, __shfl_xor_sync(0xffffffffu, mx, 2));
        float ssum = 0.f;
#pragma unroll
        for (int j = 0; j < 16; ++j) { val[j] = expf(val[j] - mx); ssum += val[j]; }
        ssum += __shfl_xor_sync(0xffffffffu, ssum, 1);
        ssum += __shfl_xor_sync(0xffffffffu, ssum, 2);
        float inv = 1.f / ssum;
        float* arow = g_att_sum + (((size_t)n * NH + h) * SEQ + s) * SEQ;
#pragma unroll
        for (int j = 0; j < 16; ++j) {
            int t = j * 4 + q4;
            float p = val[j] * inv;
            sc_s[s * LDA + t] = p;
            atomicAdd(arow + t, p);
        }
        __syncwarp();
        float oacc[8] = {};
        const float* prow = sc_s + s * LDA;
        const float* vbase = v_s + h * 32 + q4 * 8;
#pragma unroll 4
        for (int t = 0; t < 64; ++t) {
            float p = prow[t];
            const float* vr = vbase + t * LDT;
#pragma unroll
            for (int j = 0; j < 8; ++j) oacc[j] = fmaf(p, vr[j], oacc[j]);
        }
        float* rdst = res_s + s * LDT + h * 32 + q4 * 8;
#pragma unroll
        for (int j = 0; j < 8; ++j) rdst[j] = oacc[j];
        __syncwarp();
    }
    __syncthreads();

    // res -> bf16 image (U), fc via HMMA, +emb residual -> q_s, LN -> res_inter
    for (int i = tid; i < 64 * 32; i += TPB) {
        int r = i >> 5, c4 = (i & 31) * 4;
        float4 v = *(const float4*)(res_s + r * LDT + c4);
        *(__nv_bfloat162*)(ubf + r * LDB + c4)     = __floats2bfloat162_rn(v.x, v.y);
        *(__nv_bfloat162*)(ubf + r * LDB + c4 + 2) = __floats2bfloat162_rn(v.z, v.w);
    }
    {
        const uint4* ws = (const uint4*)(g_wimg + (size_t)3 * IMG);
        uint4* wd = (uint4*)wb;
        for (int i = tid; i < 2176; i += TPB) wd[i] = ws[i];
    }
    __syncthreads();
    {
        float acc[1][8][4] = {};
        wgemm64<1>(ubfAddr, wrA * 16, wbAddr, wcA * 64, acc);
        const int r0 = wrA * 16 + g;
#pragma unroll
        for (int nt = 0; nt < 8; ++nt) {
            int col = wcA * 64 + nt * 8 + t2;
            q_s[r0 * LDT + col]           = acc[0][nt][0] + emb_s[r0 * LDT + col];
            q_s[r0 * LDT + col + 1]       = acc[0][nt][1] + emb_s[r0 * LDT + col + 1];
            q_s[(r0 + 8) * LDT + col]     = acc[0][nt][2] + emb_s[(r0 + 8) * LDT + col];
            q_s[(r0 + 8) * LDT + col + 1] = acc[0][nt][3] + emb_s[(r0 + 8) * LDT + col + 1];
        }
    }
    __syncthreads();

    // LayerNorm rows -> g_res_inter
    {
        const int sr = tid >> 2, q = tid & 3;
        const float* row = q_s + sr * LDT;
        float sum = 0.f;
#pragma unroll
        for (int j = 0; j < 32; ++j) sum += row[q * 32 + j];
        sum += __shfl_xor_sync(0xffffffffu, sum, 1);
        sum += __shfl_xor_sync(0xffffffffu, sum, 2);
        float mean = sum * (1.f / 128.f);
        float vs = 0.f;
#pragma unroll
        for (int j = 0; j < 32; ++j) { float d = row[q * 32 + j] - mean; vs = fmaf(d, d, vs); }
        vs += __shfl_xor_sync(0xffffffffu, vs, 1);
        vs += __shfl_xor_sync(0xffffffffu, vs, 2);
        float rstd = rsqrtf(vs * (1.f / 128.f) + 1e-5f);
        float* outp = g_res_inter + (size_t)b * SEQ * DIM + sr * DIM;
#pragma unroll
        for (int j = 0; j < 32; ++j) {
            int c = q * 32 + j;
            outp[c] = (row[c] - mean) * rstd * lng[c] + lnb[c];
        }
    }
}

// ===========================================================================
// Kernel C: FFN + LN on res_inter via HMMA. M=128/CTA (2 neighbor tiles).
// smem: xa(34816) | hb(34816) | wb(34816) | xf(67584) | sgam/sbet(1024) | rowred(2048)
// ===========================================================================
#define C_HB   34816
#define C_WB   69632
#define C_XF   104448
#define C_SGB  172032
#define C_RED  173056
#define C_TOT  175104

__global__ void __launch_bounds__(TPB, 1) kernel_nb_ffn_tc(
    const float* __restrict__ gam, const float* __restrict__ bet,
    float* __restrict__ out) {
    extern __shared__ char smraw[];
    __nv_bfloat16* xa = (__nv_bfloat16*)smraw;
    __nv_bfloat16* hb = (__nv_bfloat16*)(smraw + C_HB);
    __nv_bfloat16* wb = (__nv_bfloat16*)(smraw + C_WB);
    float* xf     = (float*)(smraw + C_XF);
    float* sgam   = (float*)(smraw + C_SGB);
    float* sbet   = sgam + 128;
    float* rowred = (float*)(smraw + C_RED);

    const int tid = threadIdx.x;
    const int w = tid >> 5, lane = tid & 31;
    const int g = lane >> 2, t2 = (lane & 3) * 2;
    const int wr = w >> 1, wc = w & 1;   // 4 x 2 warp grid over 128x128
    const uint32_t xaAddr = smem_u32(xa);
    const uint32_t hbAddr = smem_u32(hb);
    const uint32_t wbAddr = smem_u32(wb);

    const float* xg = g_res_inter + (size_t)blockIdx.x * 128 * DIM;
    for (int i = tid; i < 128 * 32; i += TPB) {
        int r = i >> 5, c4 = (i & 31) * 4;
        float4 v = *(const float4*)(xg + r * DIM + c4);
        *(float4*)(xf + r * LDX + c4) = v;
        *(__nv_bfloat162*)(xa + r * LDB + c4)     = __floats2bfloat162_rn(v.x, v.y);
        *(__nv_bfloat162*)(xa + r * LDB + c4 + 2) = __floats2bfloat162_rn(v.z, v.w);
    }
    if (tid < 128) { sgam[tid] = gam[tid]; sbet[tid] = bet[tid]; }

    float oacc[2][8][4] = {};
#pragma unroll 1
    for (int c = 0; c < 4; ++c) {
        __syncthreads();   // xa/residual ready (iter 0) / wb free after GEMM2
        {
            const uint4* ws = (const uint4*)(g_wimg + (size_t)(4 + c) * IMG);
            uint4* wd = (uint4*)wb;
            for (int i = tid; i < 2176; i += TPB) wd[i] = ws[i];
        }
        __syncthreads();
        float hacc[2][8][4] = {};
        wgemm64<2>(xaAddr, wr * 32, wbAddr, wc * 64, hacc);
        // relu -> bf16 -> hb
#pragma unroll
        for (int mt = 0; mt < 2; ++mt) {
            int r0 = wr * 32 + mt * 16 + g;
#pragma unroll
            for (int nt = 0; nt < 8; ++nt) {
                int col = wc * 64 + nt * 8 + t2;
                float* a = hacc[mt][nt];
                *(__nv_bfloat162*)(hb + r0 * LDB + col) =
                    __floats2bfloat162_rn(fmaxf(a[0], 0.f), fmaxf(a[1], 0.f));
                *(__nv_bfloat162*)(hb + (r0 + 8) * LDB + col) =
                    __floats2bfloat162_rn(fmaxf(a[2], 0.f), fmaxf(a[3], 0.f));
            }
        }
        __syncthreads();   // hb complete, wb free
        {
            const uint4* ws = (const uint4*)(g_wimg + (size_t)(8 + c) * IMG);
            uint4* wd = (uint4*)wb;
            for (int i = tid; i < 2176; i += TPB) wd[i] = ws[i];
        }
        __syncthreads();
        wgemm64<2>(hbAddr, wr * 32, wbAddr, wc * 64, oacc);
    }
    __syncthreads();

    // epilogue: +residual, LN across fragment rows (2 warps per row), store
    float rsum[4] = {0.f, 0.f, 0.f, 0.f}, rsq[4] = {0.f, 0.f, 0.f, 0.f};
#pragma unroll
    for (int mt = 0; mt < 2; ++mt) {
        int r0 = wr * 32 + mt * 16 + g;
#pragma unroll
        for (int nt = 0; nt < 8; ++nt) {
            int col = wc * 64 + nt * 8 + t2;
            float2 x0 = *(float2*)(xf + r0 * LDX + col);
            float2 x1 = *(float2*)(xf + (r0 + 8) * LDX + col);
            float* a = oacc[mt][nt];
            a[0] += x0.x; a[1] += x0.y; a[2] += x1.x; a[3] += x1.y;
            rsum[mt * 2]     += a[0] + a[1];
            rsq[mt * 2]      += a[0] * a[0] + a[1] * a[1];
            rsum[mt * 2 + 1] += a[2] + a[3];
            rsq[mt * 2 + 1]  += a[2] * a[2] + a[3] * a[3];
        }
    }
#pragma unroll
    for (int i = 0; i < 4; ++i) {
        rsum[i] += __shfl_xor_sync(0xffffffffu, rsum[i], 1);
        rsum[i] += __shfl_xor_sync(0xffffffffu, rsum[i], 2);
        rsq[i]  += __shfl_xor_sync(0xffffffffu, rsq[i], 1);
        rsq[i]  += __shfl_xor_sync(0xffffffffu, rsq[i], 2);
    }
    if ((lane & 3) == 0) {
#pragma unroll
        for (int i = 0; i < 4; ++i) {
            int row = wr * 32 + (i >> 1) * 16 + (i & 1) * 8 + g;
            *(float2*)(rowred + row * 4 + wc * 2) = make_float2(rsum[i], rsq[i]);
        }
    }
    __syncthreads();
    float mean[4], rstd[4];
#pragma unroll
    for (int i = 0; i < 4; ++i) {
        int row = wr * 32 + (i >> 1) * 16 + (i & 1) * 8 + g;
        float s = rowred[row * 4] + rowred[row * 4 + 2];
        float q = rowred[row * 4 + 1] + rowred[row * 4 + 3];
        float m = s * (1.f / 128.f);
        mean[i] = m;
        rstd[i] = rsqrtf(fmaxf(q * (1.f / 128.f) - m * m, 0.f) + 1e-5f);
    }
    float* og = out + (size_t)blockIdx.x * 128 * DIM;
#pragma unroll
    for (int mt = 0; mt < 2; ++mt) {
        int r0 = wr * 32 + mt * 16 + g;
#pragma unroll
        for (int nt = 0; nt < 8; ++nt) {
            int col = wc * 64 + nt * 8 + t2;
            float* a = oacc[mt][nt];
            float m0 = mean[mt * 2], s0 = rstd[mt * 2];
            float m1 = mean[mt * 2 + 1], s1 = rstd[mt * 2 + 1];
            *(float2*)(og + r0 * DIM + col) =
                make_float2((a[0] - m0) * s0 * sgam[col] + sbet[col],
                            (a[1] - m0) * s0 * sgam[col + 1] + sbet[col + 1]);
            *(float2*)(og + (r0 + 8) * DIM + col) =
                make_float2((a[2] - m1) * s1 * sgam[col] + sbet[col],
                            (a[3] - m1) * s1 * sgam[col + 1] + sbet[col + 1]);
        }
    }
}

// ===========================================================================
// Scalar machinery for kernel B (unchanged)
// ===========================================================================
template <int K>
__device__ __forceinline__ void gemm_tile(const float* __restrict__ A, int lda,
                                          const float* __restrict__ B, int ldb,
                                          int rg, int cg, float acc[4][8]) {
    const int r0 = rg * 4, c0 = cg * 8;
    const float* Ar = A + r0 * lda;
    const float* Bp = B + c0;
#pragma unroll 4
    for (int k = 0; k < K; ++k) {
        float a0 = Ar[k];
        float a1 = Ar[lda + k];
        float a2 = Ar[2 * lda + k];
        float a3 = Ar[3 * lda + k];
        float4 b0 = *(const float4*)(Bp);
        float4 b1 = *(const float4*)(Bp + 4);
        Bp += ldb;
        float bb[8] = {b0.x, b0.y, b0.z, b0.w, b1.x, b1.y, b1.z, b1.w};
#pragma unroll
        for (int j = 0; j < 8; ++j) {
            acc[0][j] = fmaf(a0, bb[j], acc[0][j]);
            acc[1][j] = fmaf(a1, bb[j], acc[1][j]);
            acc[2][j] = fmaf(a2, bb[j], acc[2][j]);
            acc[3][j] = fmaf(a3, bb[j], acc[3][j]);
        }
    }
}

__device__ __forceinline__ void store_tile(float acc[4][8], float* dst, int rg, int cg) {
#pragma unroll
    for (int i = 0; i < 4; ++i)
#pragma unroll
        for (int j = 0; j < 8; ++j)
            dst[(rg * 4 + i) * LDT + cg * 8 + j] = acc[i][j];
}

__device__ __forceinline__ void load_tile(const float* __restrict__ src, float* dst) {
    for (int i = threadIdx.x; i < 64 * 32; i += TPB) {
        int row = i >> 5, c4 = i & 31;
        *(float4*)(dst + row * LDT + c4 * 4) = *(const float4*)(src + row * 128 + c4 * 4);
    }
}

__device__ __forceinline__ void layernorm_store(const float* __restrict__ buf, int ld,
                                                const float* __restrict__ gam,
                                                const float* __restrict__ bet,
                                                float* __restrict__ out) {
    const int s = threadIdx.x >> 2, q = threadIdx.x & 3;
    const float* row = buf + s * ld;
    float sum = 0.f;
#pragma unroll
    for (int j = 0; j < 32; ++j) sum += row[q * 32 + j];
    sum += __shfl_xor_sync(0xffffffffu, sum, 1);
    sum += __shfl_xor_sync(0xffffffffu, sum, 2);
    float mean = sum * (1.f / 128.f);
    float vs = 0.f;
#pragma unroll
    for (int j = 0; j < 32; ++j) { float d = row[q * 32 + j] - mean; vs = fmaf(d, d, vs); }
    vs += __shfl_xor_sync(0xffffffffu, vs, 1);
    vs += __shfl_xor_sync(0xffffffffu, vs, 2);
    float rstd = rsqrtf(vs * (1.f / 128.f) + 1e-5f);
#pragma unroll
    for (int j = 0; j < 32; ++j) {
        int c = q * 32 + j;
        out[s * 128 + c] = (row[c] - mean) * rstd * gam[c] + bet[c];
    }
}

__device__ __forceinline__ void ffn_ln_store(const float* __restrict__ x_s,
                                             float* __restrict__ h_s,
                                             const float* __restrict__ W1,
                                             const float* __restrict__ W2,
                                             const float* __restrict__ gam,
                                             const float* __restrict__ bet,
                                             float* __restrict__ out,
                                             int rg, int cg) {
    float o[4][8] = {};
#pragma unroll 1
    for (int ch = 0; ch < 4; ++ch) {
        float ha[4][8] = {};
        gemm_tile<128>(x_s, LDT, W1 + ch * 128, DFF, rg, cg, ha);
#pragma unroll
        for (int i = 0; i < 4; ++i)
#pragma unroll
            for (int j = 0; j < 8; ++j)
                h_s[(rg * 4 + i) * LDT + cg * 8 + j] = fmaxf(ha[i][j], 0.f);
        __syncthreads();
        gemm_tile<128>(h_s, LDT, W2 + (size_t)ch * 128 * 128, 128, rg, cg, o);
        __syncthreads();
    }
#pragma unroll
    for (int i = 0; i < 4; ++i)
#pragma unroll
        for (int j = 0; j < 8; ++j) {
            int idx = (rg * 4 + i) * LDT + cg * 8 + j;
            h_s[idx] = o[i][j] + x_s[idx];
        }
    __syncthreads();
    layernorm_store(h_s, LDT, gam, bet, out);
}

// ---------------------------------------------------------------------------
// Kernel B: per-agent self path (scalar, unchanged)
// ---------------------------------------------------------------------------
__global__ void __launch_bounds__(TPB) kernel_self(
    const float* __restrict__ xemb, const float* __restrict__ af,
    const float* __restrict__ WSI, const float* __restrict__ W1,
    const float* __restrict__ W2, const float* __restrict__ gam,
    const float* __restrict__ bet, float* __restrict__ out) {
    extern __shared__ float sm[];
    float* x_s  = sm;
    float* t_s  = sm + 8448;
    float* x1_s = sm + 2 * 8448;
    float* h_s  = sm + 3 * 8448;
    float* a_h  = sm + 4 * 8448;
    const int nAg = blockIdx.x;
    const int tid = threadIdx.x;
    const int rg = tid >> 4, cg = tid & 15;
    const int s = tid >> 2, q4 = tid & 3;

    load_tile(xemb + (size_t)nAg * SEQ * DIM, x_s);
    __syncthreads();

    float val[16] = {};
#pragma unroll 1
    for (int kc = 0; kc < 4; ++kc) {
        float qreg[32];
        const float* qrow = x_s + s * LDT + kc * 32;
#pragma unroll
        for (int kk = 0; kk < 32; ++kk) qreg[kk] = qrow[kk];
#pragma unroll
        for (int j = 0; j < 16; ++j) {
            int t = j * 4 + q4;
            const float* kr = x_s + t * LDT + kc * 32;
            float a = val[j];
#pragma unroll
            for (int kk = 0; kk < 32; ++kk) a = fmaf(qreg[kk], kr[kk], a);
            val[j] = a;
        }
    }
    const float isd = 0.08838834764831845f;
    float mx = val[0] * isd;
#pragma unroll
    for (int j = 0; j < 16; ++j) { val[j] *= isd; mx = fmaxf(mx, val[j]); }
    mx = fmaxf(mx, __shfl_xor_sync(0xffffffffu, mx, 1));
    mx = fmaxf(mx, __shfl_xor_sync(0xffffffffu, mx, 2));
    float ssum = 0.f;
#pragma unroll
    for (int j = 0; j < 16; ++j) { val[j] = expf(val[j] - mx); ssum += val[j]; }
    ssum += __shfl_xor_sync(0xffffffffu, ssum, 1);
    ssum += __shfl_xor_sync(0xffffffffu, ssum, 2);
    float inv = 1.f / ssum;
#pragma unroll
    for (int j = 0; j < 16; ++j) val[j] *= inv;

    const float fct = af[0] * (1.f / NNB);
    float accx[4][8] = {};
#pragma unroll 1
    for (int h = 0; h < NH; ++h) {
        const float* arow = g_att_sum + (((size_t)nAg * NH + h) * SEQ + s) * SEQ;
#pragma unroll
        for (int j = 0; j < 16; ++j) {
            int t = j * 4 + q4;
            a_h[s * LDA + t] = val[j] + fct * arow[t];
        }
        __syncthreads();
        float ta[4][8] = {};
        gemm_tile<64>(a_h, LDA, x_s, LDT, rg, cg, ta);
        store_tile(ta, t_s, rg, cg);
        __syncthreads();
        gemm_tile<128>(t_s, LDT, WSI + (size_t)h * 128 * 128, 128, rg, cg, accx);
        __syncthreads();
    }
    store_tile(accx, x1_s, rg, cg);
    __syncthreads();
    ffn_ln_store(x1_s, h_s, W1, W2, gam, bet, out + (size_t)nAg * SEQ * DIM, rg, cg);
}

// ---------------------------------------------------------------------------
extern "C" void kernel_launch(void* const* d_in, const int* in_sizes, int n_in,
                              void* d_out, int out_size) {
    const float* x_emb  = (const float*)d_in[0];
    const float* nb_emb = (const float*)d_in[1];
    const void*  mask   = d_in[2];
    const float* att_f  = (const float*)d_in[3];
    const float* WQ     = (const float*)d_in[4];
    const float* WK     = (const float*)d_in[5];
    const float* WV     = (const float*)d_in[6];
    const float* Wfc    = (const float*)d_in[7];
    const float* ln_mg  = (const float*)d_in[8];
    const float* ln_mb  = (const float*)d_in[9];
    const float* WSI    = (const float*)d_in[10];
    const float* W1s    = (const float*)d_in[11];
    const float* W2s    = (const float*)d_in[12];
    const float* ln_sg  = (const float*)d_in[13];
    const float* ln_sb  = (const float*)d_in[14];
    const float* W1i    = (const float*)d_in[15];
    const float* W2i    = (const float*)d_in[16];
    const float* ln_ig  = (const float*)d_in[17];
    const float* ln_ib  = (const float*)d_in[18];
    float* out_x  = (float*)d_out;
    float* out_nb = out_x + (size_t)NAG * SEQ * DIM;

    void* att_ptr = nullptr;
    cudaGetSymbolAddress(&att_ptr, g_att_sum);
    cudaMemsetAsync(att_ptr, 0, sizeof(float) * (size_t)NAG * NH * SEQ * SEQ, 0);
    void* flag_ptr = nullptr;
    cudaGetSymbolAddress(&flag_ptr, g_mask_is_bytes);
    cudaMemsetAsync(flag_ptr, 0, sizeof(int), 0);
    detect_mask_kernel<<<256, 256>>>((const unsigned int*)mask);
    prep_weights_kernel<<<192, 256>>>(WQ, WK, WV, Wfc, W1i, W2i);

    const size_t smB = sizeof(float) * (4 * 8448 + 64 * LDA);
    cudaFuncSetAttribute(kernel_mha,       cudaFuncAttributeMaxDynamicSharedMemorySize, A_TOT);
    cudaFuncSetAttribute(kernel_self,      cudaFuncAttributeMaxDynamicSharedMemorySize, (int)smB);
    cudaFuncSetAttribute(kernel_nb_ffn_tc, cudaFuncAttributeMaxDynamicSharedMemorySize, C_TOT);

    kernel_mha<<<NAG * NNB, TPB, A_TOT>>>(nb_emb, mask, ln_mg, ln_mb);
    kernel_nb_ffn_tc<<<NAG * NNB / 2, TPB, C_TOT>>>(ln_ig, ln_ib, out_nb);
    kernel_self<<<NAG, TPB, smB>>>(x_emb, att_f, WSI, W1s, W2s, ln_sg, ln_sb, out_x);
}

// round 7
// speedup vs baseline: 3.2736x; 1.1265x over previous
#include <cuda_runtime.h>
#include <cuda_bf16.h>
#include <cstdint>
#include <cstddef>

// Problem constants
#define NAG  128
#define NNB  16
#define SEQ  64
#define DIM  128
#define NH   4
#define DFF  512

#define TPB  256
#define LDT  132    // fp32 padded stride
#define LDA  66     // fp32 padded stride (64x64 tiles, kernel B)
#define LDB  136    // bf16 padded stride (272B rows, 16B-aligned)
#define LDX  132
#define LDP  72     // bf16 stride for P images (144B rows, 16B-aligned)
#define IMG  (128 * LDB)

#define MASK_ELEMS ((size_t)NAG * NNB * SEQ * SEQ)

// Scratch (allocation-free: __device__ globals)
static __device__ float g_att_sum[(size_t)NAG * NH * SEQ * SEQ];
static __device__ float g_res_inter[(size_t)NAG * NNB * SEQ * DIM];
static __device__ int   g_mask_is_bytes;
// 12 pre-transposed bf16 weight images [n][k], padded stride LDB:
// 0..2: WQ^T, WK^T, WV^T   3: Wfc^T   4+c: W1i^T chunk c   8+c: W2i^T chunk c
static __device__ __nv_bfloat16 g_wimg[12 * IMG];

// ===========================================================================
// mma.sync / ldmatrix helpers
// ===========================================================================
__device__ __forceinline__ uint32_t smem_u32(const void* p) {
    uint32_t a;
    asm("{ .reg .u64 t; cvta.to.shared.u64 t, %1; cvt.u32.u64 %0, t; }" : "=r"(a) : "l"(p));
    return a;
}

struct Frag4 { uint32_t x[4]; };

__device__ __forceinline__ Frag4 ldsm4(uint32_t addr) {
    Frag4 f;
    asm volatile("ldmatrix.sync.aligned.m8n8.x4.shared.b16 {%0,%1,%2,%3}, [%4];"
                 : "=r"(f.x[0]), "=r"(f.x[1]), "=r"(f.x[2]), "=r"(f.x[3]) : "r"(addr));
    return f;
}

__device__ __forceinline__ void mma16816(float c[4], const Frag4& a, uint32_t b0, uint32_t b1) {
    asm volatile("mma.sync.aligned.m16n8k16.row.col.f32.bf16.bf16.f32 "
                 "{%0,%1,%2,%3}, {%4,%5,%6,%7}, {%8,%9}, {%0,%1,%2,%3};"
                 : "+f"(c[0]), "+f"(c[1]), "+f"(c[2]), "+f"(c[3])
                 : "r"(a.x[0]), "r"(a.x[1]), "r"(a.x[2]), "r"(a.x[3]), "r"(b0), "r"(b1));
}

// Generalized warp GEMM. A: [M][lda] bf16 row-major, B: [N][ldb] bf16 = B^T
// row-major. aAddr/bAddr precomputed per-lane base addresses; strides in BYTES.
template <int MT, int NT, int KI>
__device__ __forceinline__ void wgemmX(uint32_t aAddr, int ldaB, uint32_t bAddr, int ldbB,
                                       float (*acc)[2 * NT][4]) {
#pragma unroll
    for (int k = 0; k < KI; ++k) {
        Frag4 af[MT];
#pragma unroll
        for (int mt = 0; mt < MT; ++mt)
            af[mt] = ldsm4(aAddr + mt * 16 * ldaB + k * 32);
#pragma unroll
        for (int nt = 0; nt < NT; ++nt) {
            Frag4 bf = ldsm4(bAddr + nt * 16 * ldbB + k * 32);
#pragma unroll
            for (int mt = 0; mt < MT; ++mt) {
                mma16816(acc[mt][2 * nt],     af[mt], bf.x[0], bf.x[2]);
                mma16816(acc[mt][2 * nt + 1], af[mt], bf.x[1], bf.x[3]);
            }
        }
    }
}

// ===========================================================================
// Mask dtype detection
// ===========================================================================
__global__ void detect_mask_kernel(const unsigned int* __restrict__ m) {
    const size_t nwords = MASK_ELEMS / 4;
    int found = 0;
    for (size_t i = blockIdx.x * blockDim.x + threadIdx.x; i < nwords;
         i += (size_t)gridDim.x * blockDim.x)
        if (m[i] > 1u) { found = 1; break; }
    if (found) g_mask_is_bytes = 1;
}

// ===========================================================================
// Prep: 12 transposed bf16 weight images, padded stride LDB
// ===========================================================================
__global__ void prep_weights_kernel(const float* __restrict__ WQ, const float* __restrict__ WK,
                                    const float* __restrict__ WV, const float* __restrict__ Wfc,
                                    const float* __restrict__ W1i, const float* __restrict__ W2i) {
    const int total = 12 * 128 * 32;
    for (int idx = blockIdx.x * blockDim.x + threadIdx.x; idx < total;
         idx += gridDim.x * blockDim.x) {
        int img = idx / (128 * 32);
        int rem = idx - img * (128 * 32);
        int n = rem >> 5;
        int k0 = (rem & 31) * 4;
        float v[4];
        if (img < 4) {
            const float* W = (img == 0) ? WQ : (img == 1) ? WK : (img == 2) ? WV : Wfc;
#pragma unroll
            for (int t = 0; t < 4; ++t) v[t] = W[(k0 + t) * 128 + n];
        } else if (img < 8) {
            int c = img - 4;
#pragma unroll
            for (int t = 0; t < 4; ++t) v[t] = W1i[(k0 + t) * DFF + c * 128 + n];
        } else {
            int c = img - 8;
#pragma unroll
            for (int t = 0; t < 4; ++t) v[t] = W2i[(c * 128 + k0 + t) * DIM + n];
        }
        __nv_bfloat16 b4[4];
#pragma unroll
        for (int t = 0; t < 4; ++t) b4[t] = __float2bfloat16(v[t]);
        *(uint2*)(g_wimg + (size_t)img * IMG + n * LDB + k0) = *(uint2*)b4;
    }
}

// ===========================================================================
// Kernel A v2: fully tensorized per-(agent,neighbor) MHA.
// smem layout (bytes):
//   XA  [0, 17408)        emb/res bf16 image (64 x LDB)
//   QB  [17408, 34816)    Q bf16 image
//   KB  [34816, 52224)    K bf16 image
//   PB  [17408, 54272)    8 per-warp 32xLDP P images (4608B each; aliases QB/KB
//                         + 2048B pad after KB — Q/K dead by then)
//   VT  [54272, 72704)    V^T bf16 image (128 x LDP)
//   RED aliases VT        LN reduction scratch
//   WB  [72704, 107520)   weight image
// ===========================================================================
#define AV_XA   0
#define AV_QB   17408
#define AV_KB   34816
#define AV_PB   17408
#define AV_VT   54272
#define AV_RED  54272
#define AV_WB   72704
#define AV_TOT  107520

__global__ void __launch_bounds__(TPB, 2) kernel_mha(
    const float* __restrict__ nbemb, const void* __restrict__ mask,
    const float* __restrict__ lng, const float* __restrict__ lnb) {
    extern __shared__ char smraw[];
    __nv_bfloat16* xa = (__nv_bfloat16*)(smraw + AV_XA);
    __nv_bfloat16* qb = (__nv_bfloat16*)(smraw + AV_QB);
    __nv_bfloat16* kb = (__nv_bfloat16*)(smraw + AV_KB);
    __nv_bfloat16* vt = (__nv_bfloat16*)(smraw + AV_VT);
    float* red        = (float*)(smraw + AV_RED);
    const uint32_t sb = smem_u32(smraw);

    const int b = blockIdx.x;
    const int tid = threadIdx.x;
    const int w = tid >> 5, lane = tid & 31;
    const int g = lane >> 2, t4 = lane & 3, t2 = t4 * 2;
    const int lr = lane & 15, lc = (lane >> 4) * 8;
    const int wrA = w & 3, wcA = w >> 2;    // 4x2 warp grid for 64x128 GEMMs
    const int mask_bytes = g_mask_is_bytes;
    const int n = b >> 4;

    // 1. emb -> bf16 image
    const float* src = nbemb + (size_t)b * SEQ * DIM;
    for (int i = tid; i < 64 * 32; i += TPB) {
        int r = i >> 5, c4 = (i & 31) * 4;
        float4 v = *(const float4*)(src + r * DIM + c4);
        *(__nv_bfloat162*)(xa + r * LDB + c4)     = __floats2bfloat162_rn(v.x, v.y);
        *(__nv_bfloat162*)(xa + r * LDB + c4 + 2) = __floats2bfloat162_rn(v.z, v.w);
    }
    __syncthreads();

    // 2. QKV projections -> Q,K bf16 images; V transposed bf16 image
    const uint32_t aEmb = sb + AV_XA + (uint32_t)((wrA * 16 + lr) * LDB + lc) * 2;
    const uint32_t bW   = sb + AV_WB + (uint32_t)((wcA * 64 + lr) * LDB + lc) * 2;
#pragma unroll 1
    for (int wi = 0; wi < 3; ++wi) {
        const uint4* ws = (const uint4*)(g_wimg + (size_t)wi * IMG);
        uint4* wd = (uint4*)(smraw + AV_WB);
        for (int i = tid; i < 2176; i += TPB) wd[i] = ws[i];
        __syncthreads();
        float acc[1][8][4] = {};
        wgemmX<1, 4, 8>(aEmb, LDB * 2, bW, LDB * 2, acc);
        const int r0 = wrA * 16 + g;
        if (wi < 2) {
            __nv_bfloat16* dst = (wi == 0) ? qb : kb;
#pragma unroll
            for (int j = 0; j < 8; ++j) {
                int col = wcA * 64 + j * 8 + t2;
                float* a = acc[0][j];
                *(__nv_bfloat162*)(dst + r0 * LDB + col)       = __floats2bfloat162_rn(a[0], a[1]);
                *(__nv_bfloat162*)(dst + (r0 + 8) * LDB + col) = __floats2bfloat162_rn(a[2], a[3]);
            }
        } else {
#pragma unroll
            for (int j = 0; j < 8; ++j) {
                int col = wcA * 64 + j * 8 + t2;
                float* a = acc[0][j];
                vt[col * LDP + r0]           = __float2bfloat16(a[0]);
                vt[(col + 1) * LDP + r0]     = __float2bfloat16(a[1]);
                vt[col * LDP + r0 + 8]       = __float2bfloat16(a[2]);
                vt[(col + 1) * LDP + r0 + 8] = __float2bfloat16(a[3]);
            }
        }
        __syncthreads();
    }

    // 3. scores per warp: h = w>>1, rows half*32..+31, all 64 cols
    const int h = w >> 1, half = w & 1, mrow = half * 32;
    float sc[2][8][4] = {};
    {
        uint32_t aQ = sb + AV_QB + (uint32_t)((mrow + lr) * LDB + h * 32 + lc) * 2;
        uint32_t bK = sb + AV_KB + (uint32_t)(lr * LDB + h * 32 + lc) * 2;
        wgemmX<2, 4, 2>(aQ, LDB * 2, bK, LDB * 2, sc);
    }
    // mask + scale
    const float iscale = 0.17677669529663687f;
#pragma unroll
    for (int mt = 0; mt < 2; ++mt) {
        int r0 = mrow + mt * 16 + g;
#pragma unroll
        for (int j = 0; j < 8; ++j) {
            int t = j * 8 + t2;
            bool m00, m01, m10, m11;
            if (mask_bytes) {
                const unsigned char* mp = (const unsigned char*)mask + (size_t)b * 4096;
                uchar2 u0 = *(const uchar2*)(mp + r0 * 64 + t);
                uchar2 u1 = *(const uchar2*)(mp + (r0 + 8) * 64 + t);
                m00 = u0.x; m01 = u0.y; m10 = u1.x; m11 = u1.y;
            } else {
                const int* mp = (const int*)mask + (size_t)b * 4096;
                int2 u0 = *(const int2*)(mp + r0 * 64 + t);
                int2 u1 = *(const int2*)(mp + (r0 + 8) * 64 + t);
                m00 = u0.x; m01 = u0.y; m10 = u1.x; m11 = u1.y;
            }
            float* a = sc[mt][j];
            a[0] = m00 ? a[0] * iscale : -1e9f;
            a[1] = m01 ? a[1] * iscale : -1e9f;
            a[2] = m10 ? a[2] * iscale : -1e9f;
            a[3] = m11 ? a[3] * iscale : -1e9f;
        }
    }
    // softmax per row (4 rows per thread: (mt, rh))
#pragma unroll
    for (int mt = 0; mt < 2; ++mt)
#pragma unroll
        for (int rh = 0; rh < 2; ++rh) {
            float mx = -1e30f;
#pragma unroll
            for (int j = 0; j < 8; ++j)
                mx = fmaxf(mx, fmaxf(sc[mt][j][2 * rh], sc[mt][j][2 * rh + 1]));
            mx = fmaxf(mx, __shfl_xor_sync(0xffffffffu, mx, 1));
            mx = fmaxf(mx, __shfl_xor_sync(0xffffffffu, mx, 2));
            float ssum = 0.f;
#pragma unroll
            for (int j = 0; j < 8; ++j) {
                float e0 = expf(sc[mt][j][2 * rh] - mx);
                float e1 = expf(sc[mt][j][2 * rh + 1] - mx);
                sc[mt][j][2 * rh] = e0; sc[mt][j][2 * rh + 1] = e1;
                ssum += e0 + e1;
            }
            ssum += __shfl_xor_sync(0xffffffffu, ssum, 1);
            ssum += __shfl_xor_sync(0xffffffffu, ssum, 2);
            float inv = 1.f / ssum;
#pragma unroll
            for (int j = 0; j < 8; ++j) {
                sc[mt][j][2 * rh] *= inv; sc[mt][j][2 * rh + 1] *= inv;
            }
        }
    // accumulate att sums (global atomics)
    {
        float* abase = g_att_sum + (((size_t)n * NH + h) * SEQ) * SEQ;
#pragma unroll
        for (int mt = 0; mt < 2; ++mt) {
            int r0 = mrow + mt * 16 + g;
#pragma unroll
            for (int j = 0; j < 8; ++j) {
                int t = j * 8 + t2;
                float* a = sc[mt][j];
                atomicAdd(abase + r0 * 64 + t,       a[0]);
                atomicAdd(abase + r0 * 64 + t + 1,   a[1]);
                atomicAdd(abase + (r0 + 8) * 64 + t,     a[2]);
                atomicAdd(abase + (r0 + 8) * 64 + t + 1, a[3]);
            }
        }
    }
    __syncthreads();   // all QB/KB reads complete before PB overwrite

    // P -> per-warp bf16 image (32 x LDP, aliasing dead QB/KB + pad)
    __nv_bfloat16* pbw = (__nv_bfloat16*)(smraw + AV_PB + w * (32 * LDP * 2));
#pragma unroll
    for (int mt = 0; mt < 2; ++mt) {
        int lr0 = mt * 16 + g;
#pragma unroll
        for (int j = 0; j < 8; ++j) {
            int t = j * 8 + t2;
            float* a = sc[mt][j];
            *(__nv_bfloat162*)(pbw + lr0 * LDP + t)       = __floats2bfloat162_rn(a[0], a[1]);
            *(__nv_bfloat162*)(pbw + (lr0 + 8) * LDP + t) = __floats2bfloat162_rn(a[2], a[3]);
        }
    }
    __syncthreads();

    // 4. PV: out rows mrow..+31, cols h*32..+31 -> res bf16 image (XA)
    {
        float ov[2][4][4] = {};
        uint32_t aP = sb + AV_PB + w * (32 * LDP * 2) + (uint32_t)(lr * LDP + lc) * 2;
        uint32_t bV = sb + AV_VT + (uint32_t)((h * 32 + lr) * LDP + lc) * 2;
        wgemmX<2, 2, 4>(aP, LDP * 2, bV, LDP * 2, ov);
#pragma unroll
        for (int mt = 0; mt < 2; ++mt) {
            int r0 = mrow + mt * 16 + g;
#pragma unroll
            for (int j = 0; j < 4; ++j) {
                int col = h * 32 + j * 8 + t2;
                float* a = ov[mt][j];
                *(__nv_bfloat162*)(xa + r0 * LDB + col)       = __floats2bfloat162_rn(a[0], a[1]);
                *(__nv_bfloat162*)(xa + (r0 + 8) * LDB + col) = __floats2bfloat162_rn(a[2], a[3]);
            }
        }
    }
    __syncthreads();

    // 5. fc GEMM + residual + LN -> g_res_inter
    {
        const uint4* ws = (const uint4*)(g_wimg + (size_t)3 * IMG);
        uint4* wd = (uint4*)(smraw + AV_WB);
        for (int i = tid; i < 2176; i += TPB) wd[i] = ws[i];
    }
    __syncthreads();
    {
        float fa[1][8][4] = {};
        wgemmX<1, 4, 8>(aEmb, LDB * 2, bW, LDB * 2, fa);   // XA now holds res image
        const int r0 = wrA * 16 + g;
        float rs[2] = {0.f, 0.f}, rq[2] = {0.f, 0.f};
#pragma unroll
        for (int j = 0; j < 8; ++j) {
            int col = wcA * 64 + j * 8 + t2;
            float2 e0 = *(const float2*)(src + r0 * DIM + col);
            float2 e1 = *(const float2*)(src + (r0 + 8) * DIM + col);
            float* a = fa[0][j];
            a[0] += e0.x; a[1] += e0.y; a[2] += e1.x; a[3] += e1.y;
            rs[0] += a[0] + a[1]; rq[0] += a[0] * a[0] + a[1] * a[1];
            rs[1] += a[2] + a[3]; rq[1] += a[2] * a[2] + a[3] * a[3];
        }
#pragma unroll
        for (int i = 0; i < 2; ++i) {
            rs[i] += __shfl_xor_sync(0xffffffffu, rs[i], 1);
            rs[i] += __shfl_xor_sync(0xffffffffu, rs[i], 2);
            rq[i] += __shfl_xor_sync(0xffffffffu, rq[i], 1);
            rq[i] += __shfl_xor_sync(0xffffffffu, rq[i], 2);
        }
        if (t4 == 0) {
            *(float2*)(red + r0 * 4 + wcA * 2)       = make_float2(rs[0], rq[0]);
            *(float2*)(red + (r0 + 8) * 4 + wcA * 2) = make_float2(rs[1], rq[1]);
        }
        __syncthreads();
        float mean[2], rstd[2];
#pragma unroll
        for (int i = 0; i < 2; ++i) {
            int r = r0 + i * 8;
            float s = red[r * 4] + red[r * 4 + 2];
            float q = red[r * 4 + 1] + red[r * 4 + 3];
            float m = s * (1.f / 128.f);
            mean[i] = m;
            rstd[i] = rsqrtf(fmaxf(q * (1.f / 128.f) - m * m, 0.f) + 1e-5f);
        }
        float* og = g_res_inter + (size_t)b * SEQ * DIM;
#pragma unroll
        for (int j = 0; j < 8; ++j) {
            int col = wcA * 64 + j * 8 + t2;
            float2 gm = *(const float2*)(lng + col);
            float2 bt = *(const float2*)(lnb + col);
            float* a = fa[0][j];
            *(float2*)(og + r0 * DIM + col) =
                make_float2((a[0] - mean[0]) * rstd[0] * gm.x + bt.x,
                            (a[1] - mean[0]) * rstd[0] * gm.y + bt.y);
            *(float2*)(og + (r0 + 8) * DIM + col) =
                make_float2((a[2] - mean[1]) * rstd[1] * gm.x + bt.x,
                            (a[3] - mean[1]) * rstd[1] * gm.y + bt.y);
        }
    }
}

// ===========================================================================
// Kernel C: FFN + LN on res_inter via HMMA (unchanged from R5)
// ===========================================================================
#define C_HB   34816
#define C_WB   69632
#define C_XF   104448
#define C_SGB  172032
#define C_RED  173056
#define C_TOT  175104

__global__ void __launch_bounds__(TPB, 1) kernel_nb_ffn_tc(
    const float* __restrict__ gam, const float* __restrict__ bet,
    float* __restrict__ out) {
    extern __shared__ char smraw[];
    __nv_bfloat16* xa = (__nv_bfloat16*)smraw;
    __nv_bfloat16* hb = (__nv_bfloat16*)(smraw + C_HB);
    __nv_bfloat16* wb = (__nv_bfloat16*)(smraw + C_WB);
    float* xf     = (float*)(smraw + C_XF);
    float* sgam   = (float*)(smraw + C_SGB);
    float* sbet   = sgam + 128;
    float* rowred = (float*)(smraw + C_RED);

    const int tid = threadIdx.x;
    const int w = tid >> 5, lane = tid & 31;
    const int g = lane >> 2, t2 = (lane & 3) * 2;
    const int wr = w >> 1, wc = w & 1;
    const int lr = lane & 15, lc = (lane >> 4) * 8;
    const uint32_t sb = smem_u32(smraw);
    const uint32_t xaA = sb + (uint32_t)((wr * 32 + lr) * LDB + lc) * 2;
    const uint32_t hbA = sb + C_HB + (uint32_t)((wr * 32 + lr) * LDB + lc) * 2;
    const uint32_t wbA = sb + C_WB + (uint32_t)((wc * 64 + lr) * LDB + lc) * 2;

    const float* xg = g_res_inter + (size_t)blockIdx.x * 128 * DIM;
    for (int i = tid; i < 128 * 32; i += TPB) {
        int r = i >> 5, c4 = (i & 31) * 4;
        float4 v = *(const float4*)(xg + r * DIM + c4);
        *(float4*)(xf + r * LDX + c4) = v;
        *(__nv_bfloat162*)(xa + r * LDB + c4)     = __floats2bfloat162_rn(v.x, v.y);
        *(__nv_bfloat162*)(xa + r * LDB + c4 + 2) = __floats2bfloat162_rn(v.z, v.w);
    }
    if (tid < 128) { sgam[tid] = gam[tid]; sbet[tid] = bet[tid]; }

    float oacc[2][8][4] = {};
#pragma unroll 1
    for (int c = 0; c < 4; ++c) {
        __syncthreads();
        {
            const uint4* ws = (const uint4*)(g_wimg + (size_t)(4 + c) * IMG);
            uint4* wd = (uint4*)wb;
            for (int i = tid; i < 2176; i += TPB) wd[i] = ws[i];
        }
        __syncthreads();
        float hacc[2][8][4] = {};
        wgemmX<2, 4, 8>(xaA, LDB * 2, wbA, LDB * 2, hacc);
#pragma unroll
        for (int mt = 0; mt < 2; ++mt) {
            int r0 = wr * 32 + mt * 16 + g;
#pragma unroll
            for (int nt = 0; nt < 8; ++nt) {
                int col = wc * 64 + nt * 8 + t2;
                float* a = hacc[mt][nt];
                *(__nv_bfloat162*)(hb + r0 * LDB + col) =
                    __floats2bfloat162_rn(fmaxf(a[0], 0.f), fmaxf(a[1], 0.f));
                *(__nv_bfloat162*)(hb + (r0 + 8) * LDB + col) =
                    __floats2bfloat162_rn(fmaxf(a[2], 0.f), fmaxf(a[3], 0.f));
            }
        }
        __syncthreads();
        {
            const uint4* ws = (const uint4*)(g_wimg + (size_t)(8 + c) * IMG);
            uint4* wd = (uint4*)wb;
            for (int i = tid; i < 2176; i += TPB) wd[i] = ws[i];
        }
        __syncthreads();
        wgemmX<2, 4, 8>(hbA, LDB * 2, wbA, LDB * 2, oacc);
    }
    __syncthreads();

    float rsum[4] = {0.f, 0.f, 0.f, 0.f}, rsq[4] = {0.f, 0.f, 0.f, 0.f};
#pragma unroll
    for (int mt = 0; mt < 2; ++mt) {
        int r0 = wr * 32 + mt * 16 + g;
#pragma unroll
        for (int nt = 0; nt < 8; ++nt) {
            int col = wc * 64 + nt * 8 + t2;
            float2 x0 = *(float2*)(xf + r0 * LDX + col);
            float2 x1 = *(float2*)(xf + (r0 + 8) * LDX + col);
            float* a = oacc[mt][nt];
            a[0] += x0.x; a[1] += x0.y; a[2] += x1.x; a[3] += x1.y;
            rsum[mt * 2]     += a[0] + a[1];
            rsq[mt * 2]      += a[0] * a[0] + a[1] * a[1];
            rsum[mt * 2 + 1] += a[2] + a[3];
            rsq[mt * 2 + 1]  += a[2] * a[2] + a[3] * a[3];
        }
    }
#pragma unroll
    for (int i = 0; i < 4; ++i) {
        rsum[i] += __shfl_xor_sync(0xffffffffu, rsum[i], 1);
        rsum[i] += __shfl_xor_sync(0xffffffffu, rsum[i], 2);
        rsq[i]  += __shfl_xor_sync(0xffffffffu, rsq[i], 1);
        rsq[i]  += __shfl_xor_sync(0xffffffffu, rsq[i], 2);
    }
    if ((lane & 3) == 0) {
#pragma unroll
        for (int i = 0; i < 4; ++i) {
            int row = wr * 32 + (i >> 1) * 16 + (i & 1) * 8 + g;
            *(float2*)(rowred + row * 4 + wc * 2) = make_float2(rsum[i], rsq[i]);
        }
    }
    __syncthreads();
    float mean[4], rstd[4];
#pragma unroll
    for (int i = 0; i < 4; ++i) {
        int row = wr * 32 + (i >> 1) * 16 + (i & 1) * 8 + g;
        float s = rowred[row * 4] + rowred[row * 4 + 2];
        float q = rowred[row * 4 + 1] + rowred[row * 4 + 3];
        float m = s * (1.f / 128.f);
        mean[i] = m;
        rstd[i] = rsqrtf(fmaxf(q * (1.f / 128.f) - m * m, 0.f) + 1e-5f);
    }
    float* og = out + (size_t)blockIdx.x * 128 * DIM;
#pragma unroll
    for (int mt = 0; mt < 2; ++mt) {
        int r0 = wr * 32 + mt * 16 + g;
#pragma unroll
        for (int nt = 0; nt < 8; ++nt) {
            int col = wc * 64 + nt * 8 + t2;
            float* a = oacc[mt][nt];
            float m0 = mean[mt * 2], s0 = rstd[mt * 2];
            float m1 = mean[mt * 2 + 1], s1 = rstd[mt * 2 + 1];
            *(float2*)(og + r0 * DIM + col) =
                make_float2((a[0] - m0) * s0 * sgam[col] + sbet[col],
                            (a[1] - m0) * s0 * sgam[col + 1] + sbet[col + 1]);
            *(float2*)(og + (r0 + 8) * DIM + col) =
                make_float2((a[2] - m1) * s1 * sgam[col] + sbet[col],
                            (a[3] - m1) * s1 * sgam[col + 1] + sbet[col + 1]);
        }
    }
}

// ===========================================================================
// Scalar machinery for kernel B (unchanged)
// ===========================================================================
template <int K>
__device__ __forceinline__ void gemm_tile(const float* __restrict__ A, int lda,
                                          const float* __restrict__ B, int ldb,
                                          int rg, int cg, float acc[4][8]) {
    const int r0 = rg * 4, c0 = cg * 8;
    const float* Ar = A + r0 * lda;
    const float* Bp = B + c0;
#pragma unroll 4
    for (int k = 0; k < K; ++k) {
        float a0 = Ar[k];
        float a1 = Ar[lda + k];
        float a2 = Ar[2 * lda + k];
        float a3 = Ar[3 * lda + k];
        float4 b0 = *(const float4*)(Bp);
        float4 b1 = *(const float4*)(Bp + 4);
        Bp += ldb;
        float bb[8] = {b0.x, b0.y, b0.z, b0.w, b1.x, b1.y, b1.z, b1.w};
#pragma unroll
        for (int j = 0; j < 8; ++j) {
            acc[0][j] = fmaf(a0, bb[j], acc[0][j]);
            acc[1][j] = fmaf(a1, bb[j], acc[1][j]);
            acc[2][j] = fmaf(a2, bb[j], acc[2][j]);
            acc[3][j] = fmaf(a3, bb[j], acc[3][j]);
        }
    }
}

__device__ __forceinline__ void store_tile(float acc[4][8], float* dst, int rg, int cg) {
#pragma unroll
    for (int i = 0; i < 4; ++i)
#pragma unroll
        for (int j = 0; j < 8; ++j)
            dst[(rg * 4 + i) * LDT + cg * 8 + j] = acc[i][j];
}

__device__ __forceinline__ void load_tile(const float* __restrict__ src, float* dst) {
    for (int i = threadIdx.x; i < 64 * 32; i += TPB) {
        int row = i >> 5, c4 = i & 31;
        *(float4*)(dst + row * LDT + c4 * 4) = *(const float4*)(src + row * 128 + c4 * 4);
    }
}

__device__ __forceinline__ void layernorm_store(const float* __restrict__ buf, int ld,
                                                const float* __restrict__ gam,
                                                const float* __restrict__ bet,
                                                float* __restrict__ out) {
    const int s = threadIdx.x >> 2, q = threadIdx.x & 3;
    const float* row = buf + s * ld;
    float sum = 0.f;
#pragma unroll
    for (int j = 0; j < 32; ++j) sum += row[q * 32 + j];
    sum += __shfl_xor_sync(0xffffffffu, sum, 1);
    sum += __shfl_xor_sync(0xffffffffu, sum, 2);
    float mean = sum * (1.f / 128.f);
    float vs = 0.f;
#pragma unroll
    for (int j = 0; j < 32; ++j) { float d = row[q * 32 + j] - mean; vs = fmaf(d, d, vs); }
    vs += __shfl_xor_sync(0xffffffffu, vs, 1);
    vs += __shfl_xor_sync(0xffffffffu, vs, 2);
    float rstd = rsqrtf(vs * (1.f / 128.f) + 1e-5f);
#pragma unroll
    for (int j = 0; j < 32; ++j) {
        int c = q * 32 + j;
        out[s * 128 + c] = (row[c] - mean) * rstd * gam[c] + bet[c];
    }
}

__device__ __forceinline__ void ffn_ln_store(const float* __restrict__ x_s,
                                             float* __restrict__ h_s,
                                             const float* __restrict__ W1,
                                             const float* __restrict__ W2,
                                             const float* __restrict__ gam,
                                             const float* __restrict__ bet,
                                             float* __restrict__ out,
                                             int rg, int cg) {
    float o[4][8] = {};
#pragma unroll 1
    for (int ch = 0; ch < 4; ++ch) {
        float ha[4][8] = {};
        gemm_tile<128>(x_s, LDT, W1 + ch * 128, DFF, rg, cg, ha);
#pragma unroll
        for (int i = 0; i < 4; ++i)
#pragma unroll
            for (int j = 0; j < 8; ++j)
                h_s[(rg * 4 + i) * LDT + cg * 8 + j] = fmaxf(ha[i][j], 0.f);
        __syncthreads();
        gemm_tile<128>(h_s, LDT, W2 + (size_t)ch * 128 * 128, 128, rg, cg, o);
        __syncthreads();
    }
#pragma unroll
    for (int i = 0; i < 4; ++i)
#pragma unroll
        for (int j = 0; j < 8; ++j) {
            int idx = (rg * 4 + i) * LDT + cg * 8 + j;
            h_s[idx] = o[i][j] + x_s[idx];
        }
    __syncthreads();
    layernorm_store(h_s, LDT, gam, bet, out);
}

// ---------------------------------------------------------------------------
// Kernel B: per-agent self path (scalar, unchanged)
// ---------------------------------------------------------------------------
__global__ void __launch_bounds__(TPB) kernel_self(
    const float* __restrict__ xemb, const float* __restrict__ af,
    const float* __restrict__ WSI, const float* __restrict__ W1,
    const float* __restrict__ W2, const float* __restrict__ gam,
    const float* __restrict__ bet, float* __restrict__ out) {
    extern __shared__ float sm[];
    float* x_s  = sm;
    float* t_s  = sm + 8448;
    float* x1_s = sm + 2 * 8448;
    float* h_s  = sm + 3 * 8448;
    float* a_h  = sm + 4 * 8448;
    const int nAg = blockIdx.x;
    const int tid = threadIdx.x;
    const int rg = tid >> 4, cg = tid & 15;
    const int s = tid >> 2, q4 = tid & 3;

    load_tile(xemb + (size_t)nAg * SEQ * DIM, x_s);
    __syncthreads();

    float val[16] = {};
#pragma unroll 1
    for (int kc = 0; kc < 4; ++kc) {
        float qreg[32];
        const float* qrow = x_s + s * LDT + kc * 32;
#pragma unroll
        for (int kk = 0; kk < 32; ++kk) qreg[kk] = qrow[kk];
#pragma unroll
        for (int j = 0; j < 16; ++j) {
            int t = j * 4 + q4;
            const float* kr = x_s + t * LDT + kc * 32;
            float a = val[j];
#pragma unroll
            for (int kk = 0; kk < 32; ++kk) a = fmaf(qreg[kk], kr[kk], a);
            val[j] = a;
        }
    }
    const float isd = 0.08838834764831845f;
    float mx = val[0] * isd;
#pragma unroll
    for (int j = 0; j < 16; ++j) { val[j] *= isd; mx = fmaxf(mx, val[j]); }
    mx = fmaxf(mx, __shfl_xor_sync(0xffffffffu, mx, 1));
    mx = fmaxf(mx, __shfl_xor_sync(0xffffffffu, mx, 2));
    float ssum = 0.f;
#pragma unroll
    for (int j = 0; j < 16; ++j) { val[j] = expf(val[j] - mx); ssum += val[j]; }
    ssum += __shfl_xor_sync(0xffffffffu, ssum, 1);
    ssum += __shfl_xor_sync(0xffffffffu, ssum, 2);
    float inv = 1.f / ssum;
#pragma unroll
    for (int j = 0; j < 16; ++j) val[j] *= inv;

    const float fct = af[0] * (1.f / NNB);
    float accx[4][8] = {};
#pragma unroll 1
    for (int h = 0; h < NH; ++h) {
        const float* arow = g_att_sum + (((size_t)nAg * NH + h) * SEQ + s) * SEQ;
#pragma unroll
        for (int j = 0; j < 16; ++j) {
            int t = j * 4 + q4;
            a_h[s * LDA + t] = val[j] + fct * arow[t];
        }
        __syncthreads();
        float ta[4][8] = {};
        gemm_tile<64>(a_h, LDA, x_s, LDT, rg, cg, ta);
        store_tile(ta, t_s, rg, cg);
        __syncthreads();
        gemm_tile<128>(t_s, LDT, WSI + (size_t)h * 128 * 128, 128, rg, cg, accx);
        __syncthreads();
    }
    store_tile(accx, x1_s, rg, cg);
    __syncthreads();
    ffn_ln_store(x1_s, h_s, W1, W2, gam, bet, out + (size_t)nAg * SEQ * DIM, rg, cg);
}

// ---------------------------------------------------------------------------
extern "C" void kernel_launch(void* const* d_in, const int* in_sizes, int n_in,
                              void* d_out, int out_size) {
    const float* x_emb  = (const float*)d_in[0];
    const float* nb_emb = (const float*)d_in[1];
    const void*  mask   = d_in[2];
    const float* att_f  = (const float*)d_in[3];
    const float* WQ     = (const float*)d_in[4];
    const float* WK     = (const float*)d_in[5];
    const float* WV     = (const float*)d_in[6];
    const float* Wfc    = (const float*)d_in[7];
    const float* ln_mg  = (const float*)d_in[8];
    const float* ln_mb  = (const float*)d_in[9];
    const float* WSI    = (const float*)d_in[10];
    const float* W1s    = (const float*)d_in[11];
    const float* W2s    = (const float*)d_in[12];
    const float* ln_sg  = (const float*)d_in[13];
    const float* ln_sb  = (const float*)d_in[14];
    const float* W1i    = (const float*)d_in[15];
    const float* W2i    = (const float*)d_in[16];
    const float* ln_ig  = (const float*)d_in[17];
    const float* ln_ib  = (const float*)d_in[18];
    float* out_x  = (float*)d_out;
    float* out_nb = out_x + (size_t)NAG * SEQ * DIM;

    void* att_ptr = nullptr;
    cudaGetSymbolAddress(&att_ptr, g_att_sum);
    cudaMemsetAsync(att_ptr, 0, sizeof(float) * (size_t)NAG * NH * SEQ * SEQ, 0);
    void* flag_ptr = nullptr;
    cudaGetSymbolAddress(&flag_ptr, g_mask_is_bytes);
    cudaMemsetAsync(flag_ptr, 0, sizeof(int), 0);
    detect_mask_kernel<<<256, 256>>>((const unsigned int*)mask);
    prep_weights_kernel<<<192, 256>>>(WQ, WK, WV, Wfc, W1i, W2i);

    const size_t smB = sizeof(float) * (4 * 8448 + 64 * LDA);
    cudaFuncSetAttribute(kernel_mha,       cudaFuncAttributeMaxDynamicSharedMemorySize, AV_TOT);
    cudaFuncSetAttribute(kernel_self,      cudaFuncAttributeMaxDynamicSharedMemorySize, (int)smB);
    cudaFuncSetAttribute(kernel_nb_ffn_tc, cudaFuncAttributeMaxDynamicSharedMemorySize, C_TOT);

    kernel_mha<<<NAG * NNB, TPB, AV_TOT>>>(nb_emb, mask, ln_mg, ln_mb);
    kernel_nb_ffn_tc<<<NAG * NNB / 2, TPB, C_TOT>>>(ln_ig, ln_ib, out_nb);
    kernel_self<<<NAG, TPB, smB>>>(x_emb, att_f, WSI, W1s, W2s, ln_sg, ln_sb, out_x);
}

// round 9
// speedup vs baseline: 4.8867x; 1.4928x over previous
#include <cuda_runtime.h>
#include <cuda_bf16.h>
#include <cstdint>
#include <cstddef>

// Problem constants
#define NAG  128
#define NNB  16
#define SEQ  64
#define DIM  128
#define NH   4
#define DFF  512

#define TPB  256
#define TPBC 512
#define LDT  132    // fp32 padded stride
#define LDA  66     // fp32 padded stride (64x64 tiles, kernel B)
#define LDB  136    // bf16 padded stride (272B rows, 16B-aligned)
#define LDX  132
#define LDP  72     // bf16 stride for P images (144B rows, 16B-aligned)
#define IMG  (128 * LDB)

#define MASK_ELEMS ((size_t)NAG * NNB * SEQ * SEQ)

// Scratch (allocation-free: __device__ globals)
static __device__ float g_att_sum[(size_t)NAG * NH * SEQ * SEQ];
static __device__ float g_res_inter[(size_t)NAG * NNB * SEQ * DIM];
static __device__ int   g_mask_is_bytes;
// 12 pre-transposed bf16 weight images [n][k], padded stride LDB:
// 0..2: WQ^T, WK^T, WV^T   3: Wfc^T   4+c: W1i^T chunk c   8+c: W2i^T chunk c
static __device__ __nv_bfloat16 g_wimg[12 * IMG];

// Side stream + events for B/C overlap (created at static init — outside
// graph capture; not device memory).
struct StreamInit {
    cudaStream_t s;
    cudaEvent_t evA, evB;
    StreamInit() {
        cudaStreamCreateWithFlags(&s, cudaStreamNonBlocking);
        cudaEventCreateWithFlags(&evA, cudaEventDisableTiming);
        cudaEventCreateWithFlags(&evB, cudaEventDisableTiming);
    }
};
static StreamInit g_si;

// ===========================================================================
// mma.sync / ldmatrix helpers
// ===========================================================================
__device__ __forceinline__ uint32_t smem_u32(const void* p) {
    uint32_t a;
    asm("{ .reg .u64 t; cvta.to.shared.u64 t, %1; cvt.u32.u64 %0, t; }" : "=r"(a) : "l"(p));
    return a;
}

struct Frag4 { uint32_t x[4]; };

__device__ __forceinline__ Frag4 ldsm4(uint32_t addr) {
    Frag4 f;
    asm volatile("ldmatrix.sync.aligned.m8n8.x4.shared.b16 {%0,%1,%2,%3}, [%4];"
                 : "=r"(f.x[0]), "=r"(f.x[1]), "=r"(f.x[2]), "=r"(f.x[3]) : "r"(addr));
    return f;
}

__device__ __forceinline__ void mma16816(float c[4], const Frag4& a, uint32_t b0, uint32_t b1) {
    asm volatile("mma.sync.aligned.m16n8k16.row.col.f32.bf16.bf16.f32 "
                 "{%0,%1,%2,%3}, {%4,%5,%6,%7}, {%8,%9}, {%0,%1,%2,%3};"
                 : "+f"(c[0]), "+f"(c[1]), "+f"(c[2]), "+f"(c[3])
                 : "r"(a.x[0]), "r"(a.x[1]), "r"(a.x[2]), "r"(a.x[3]), "r"(b0), "r"(b1));
}

// Generalized warp GEMM. A: [M][lda] bf16 row-major, B: [N][ldb] bf16 = B^T
// row-major. aAddr/bAddr precomputed per-lane base addresses; strides in BYTES.
template <int MT, int NT, int KI>
__device__ __forceinline__ void wgemmX(uint32_t aAddr, int ldaB, uint32_t bAddr, int ldbB,
                                       float (*acc)[2 * NT][4]) {
#pragma unroll
    for (int k = 0; k < KI; ++k) {
        Frag4 af[MT];
#pragma unroll
        for (int mt = 0; mt < MT; ++mt)
            af[mt] = ldsm4(aAddr + mt * 16 * ldaB + k * 32);
#pragma unroll
        for (int nt = 0; nt < NT; ++nt) {
            Frag4 bf = ldsm4(bAddr + nt * 16 * ldbB + k * 32);
#pragma unroll
            for (int mt = 0; mt < MT; ++mt) {
                mma16816(acc[mt][2 * nt],     af[mt], bf.x[0], bf.x[2]);
                mma16816(acc[mt][2 * nt + 1], af[mt], bf.x[1], bf.x[3]);
            }
        }
    }
}

// ===========================================================================
// Mask dtype detection
// ===========================================================================
__global__ void detect_mask_kernel(const unsigned int* __restrict__ m) {
    const size_t nwords = MASK_ELEMS / 4;
    int found = 0;
    for (size_t i = blockIdx.x * blockDim.x + threadIdx.x; i < nwords;
         i += (size_t)gridDim.x * blockDim.x)
        if (m[i] > 1u) { found = 1; break; }
    if (found) g_mask_is_bytes = 1;
}

// ===========================================================================
// Prep: 12 transposed bf16 weight images, padded stride LDB
// ===========================================================================
__global__ void prep_weights_kernel(const float* __restrict__ WQ, const float* __restrict__ WK,
                                    const float* __restrict__ WV, const float* __restrict__ Wfc,
                                    const float* __restrict__ W1i, const float* __restrict__ W2i) {
    const int total = 12 * 128 * 32;
    for (int idx = blockIdx.x * blockDim.x + threadIdx.x; idx < total;
         idx += gridDim.x * blockDim.x) {
        int img = idx / (128 * 32);
        int rem = idx - img * (128 * 32);
        int n = rem >> 5;
        int k0 = (rem & 31) * 4;
        float v[4];
        if (img < 4) {
            const float* W = (img == 0) ? WQ : (img == 1) ? WK : (img == 2) ? WV : Wfc;
#pragma unroll
            for (int t = 0; t < 4; ++t) v[t] = W[(k0 + t) * 128 + n];
        } else if (img < 8) {
            int c = img - 4;
#pragma unroll
            for (int t = 0; t < 4; ++t) v[t] = W1i[(k0 + t) * DFF + c * 128 + n];
        } else {
            int c = img - 8;
#pragma unroll
            for (int t = 0; t < 4; ++t) v[t] = W2i[(c * 128 + k0 + t) * DIM + n];
        }
        __nv_bfloat16 b4[4];
#pragma unroll
        for (int t = 0; t < 4; ++t) b4[t] = __float2bfloat16(v[t]);
        *(uint2*)(g_wimg + (size_t)img * IMG + n * LDB + k0) = *(uint2*)b4;
    }
}

// ===========================================================================
// Kernel A: fully tensorized per-(agent,neighbor) MHA (unchanged from R7)
// ===========================================================================
#define AV_XA   0
#define AV_QB   17408
#define AV_KB   34816
#define AV_PB   17408
#define AV_VT   54272
#define AV_RED  54272
#define AV_WB   72704
#define AV_TOT  107520

__global__ void __launch_bounds__(TPB, 2) kernel_mha(
    const float* __restrict__ nbemb, const void* __restrict__ mask,
    const float* __restrict__ lng, const float* __restrict__ lnb) {
    extern __shared__ char smraw[];
    __nv_bfloat16* xa = (__nv_bfloat16*)(smraw + AV_XA);
    __nv_bfloat16* qb = (__nv_bfloat16*)(smraw + AV_QB);
    __nv_bfloat16* kb = (__nv_bfloat16*)(smraw + AV_KB);
    __nv_bfloat16* vt = (__nv_bfloat16*)(smraw + AV_VT);
    float* red        = (float*)(smraw + AV_RED);
    const uint32_t sb = smem_u32(smraw);

    const int b = blockIdx.x;
    const int tid = threadIdx.x;
    const int w = tid >> 5, lane = tid & 31;
    const int g = lane >> 2, t4 = lane & 3, t2 = t4 * 2;
    const int lr = lane & 15, lc = (lane >> 4) * 8;
    const int wrA = w & 3, wcA = w >> 2;
    const int mask_bytes = g_mask_is_bytes;
    const int n = b >> 4;

    const float* src = nbemb + (size_t)b * SEQ * DIM;
    for (int i = tid; i < 64 * 32; i += TPB) {
        int r = i >> 5, c4 = (i & 31) * 4;
        float4 v = *(const float4*)(src + r * DIM + c4);
        *(__nv_bfloat162*)(xa + r * LDB + c4)     = __floats2bfloat162_rn(v.x, v.y);
        *(__nv_bfloat162*)(xa + r * LDB + c4 + 2) = __floats2bfloat162_rn(v.z, v.w);
    }
    __syncthreads();

    const uint32_t aEmb = sb + AV_XA + (uint32_t)((wrA * 16 + lr) * LDB + lc) * 2;
    const uint32_t bW   = sb + AV_WB + (uint32_t)((wcA * 64 + lr) * LDB + lc) * 2;
#pragma unroll 1
    for (int wi = 0; wi < 3; ++wi) {
        const uint4* ws = (const uint4*)(g_wimg + (size_t)wi * IMG);
        uint4* wd = (uint4*)(smraw + AV_WB);
        for (int i = tid; i < 2176; i += TPB) wd[i] = ws[i];
        __syncthreads();
        float acc[1][8][4] = {};
        wgemmX<1, 4, 8>(aEmb, LDB * 2, bW, LDB * 2, acc);
        const int r0 = wrA * 16 + g;
        if (wi < 2) {
            __nv_bfloat16* dst = (wi == 0) ? qb : kb;
#pragma unroll
            for (int j = 0; j < 8; ++j) {
                int col = wcA * 64 + j * 8 + t2;
                float* a = acc[0][j];
                *(__nv_bfloat162*)(dst + r0 * LDB + col)       = __floats2bfloat162_rn(a[0], a[1]);
                *(__nv_bfloat162*)(dst + (r0 + 8) * LDB + col) = __floats2bfloat162_rn(a[2], a[3]);
            }
        } else {
#pragma unroll
            for (int j = 0; j < 8; ++j) {
                int col = wcA * 64 + j * 8 + t2;
                float* a = acc[0][j];
                vt[col * LDP + r0]           = __float2bfloat16(a[0]);
                vt[(col + 1) * LDP + r0]     = __float2bfloat16(a[1]);
                vt[col * LDP + r0 + 8]       = __float2bfloat16(a[2]);
                vt[(col + 1) * LDP + r0 + 8] = __float2bfloat16(a[3]);
            }
        }
        __syncthreads();
    }

    const int h = w >> 1, half = w & 1, mrow = half * 32;
    float sc[2][8][4] = {};
    {
        uint32_t aQ = sb + AV_QB + (uint32_t)((mrow + lr) * LDB + h * 32 + lc) * 2;
        uint32_t bK = sb + AV_KB + (uint32_t)(lr * LDB + h * 32 + lc) * 2;
        wgemmX<2, 4, 2>(aQ, LDB * 2, bK, LDB * 2, sc);
    }
    const float iscale = 0.17677669529663687f;
#pragma unroll
    for (int mt = 0; mt < 2; ++mt) {
        int r0 = mrow + mt * 16 + g;
#pragma unroll
        for (int j = 0; j < 8; ++j) {
            int t = j * 8 + t2;
            bool m00, m01, m10, m11;
            if (mask_bytes) {
                const unsigned char* mp = (const unsigned char*)mask + (size_t)b * 4096;
                uchar2 u0 = *(const uchar2*)(mp + r0 * 64 + t);
                uchar2 u1 = *(const uchar2*)(mp + (r0 + 8) * 64 + t);
                m00 = u0.x; m01 = u0.y; m10 = u1.x; m11 = u1.y;
            } else {
                const int* mp = (const int*)mask + (size_t)b * 4096;
                int2 u0 = *(const int2*)(mp + r0 * 64 + t);
                int2 u1 = *(const int2*)(mp + (r0 + 8) * 64 + t);
                m00 = u0.x; m01 = u0.y; m10 = u1.x; m11 = u1.y;
            }
            float* a = sc[mt][j];
            a[0] = m00 ? a[0] * iscale : -1e9f;
            a[1] = m01 ? a[1] * iscale : -1e9f;
            a[2] = m10 ? a[2] * iscale : -1e9f;
            a[3] = m11 ? a[3] * iscale : -1e9f;
        }
    }
#pragma unroll
    for (int mt = 0; mt < 2; ++mt)
#pragma unroll
        for (int rh = 0; rh < 2; ++rh) {
            float mx = -1e30f;
#pragma unroll
            for (int j = 0; j < 8; ++j)
                mx = fmaxf(mx, fmaxf(sc[mt][j][2 * rh], sc[mt][j][2 * rh + 1]));
            mx = fmaxf(mx, __shfl_xor_sync(0xffffffffu, mx, 1));
            mx = fmaxf(mx, __shfl_xor_sync(0xffffffffu, mx, 2));
            float ssum = 0.f;
#pragma unroll
            for (int j = 0; j < 8; ++j) {
                float e0 = expf(sc[mt][j][2 * rh] - mx);
                float e1 = expf(sc[mt][j][2 * rh + 1] - mx);
                sc[mt][j][2 * rh] = e0; sc[mt][j][2 * rh + 1] = e1;
                ssum += e0 + e1;
            }
            ssum += __shfl_xor_sync(0xffffffffu, ssum, 1);
            ssum += __shfl_xor_sync(0xffffffffu, ssum, 2);
            float inv = 1.f / ssum;
#pragma unroll
            for (int j = 0; j < 8; ++j) {
                sc[mt][j][2 * rh] *= inv; sc[mt][j][2 * rh + 1] *= inv;
            }
        }
    {
        float* abase = g_att_sum + (((size_t)n * NH + h) * SEQ) * SEQ;
#pragma unroll
        for (int mt = 0; mt < 2; ++mt) {
            int r0 = mrow + mt * 16 + g;
#pragma unroll
            for (int j = 0; j < 8; ++j) {
                int t = j * 8 + t2;
                float* a = sc[mt][j];
                atomicAdd(abase + r0 * 64 + t,       a[0]);
                atomicAdd(abase + r0 * 64 + t + 1,   a[1]);
                atomicAdd(abase + (r0 + 8) * 64 + t,     a[2]);
                atomicAdd(abase + (r0 + 8) * 64 + t + 1, a[3]);
            }
        }
    }
    __syncthreads();

    __nv_bfloat16* pbw = (__nv_bfloat16*)(smraw + AV_PB + w * (32 * LDP * 2));
#pragma unroll
    for (int mt = 0; mt < 2; ++mt) {
        int lr0 = mt * 16 + g;
#pragma unroll
        for (int j = 0; j < 8; ++j) {
            int t = j * 8 + t2;
            float* a = sc[mt][j];
            *(__nv_bfloat162*)(pbw + lr0 * LDP + t)       = __floats2bfloat162_rn(a[0], a[1]);
            *(__nv_bfloat162*)(pbw + (lr0 + 8) * LDP + t) = __floats2bfloat162_rn(a[2], a[3]);
        }
    }
    __syncthreads();

    {
        float ov[2][4][4] = {};
        uint32_t aP = sb + AV_PB + w * (32 * LDP * 2) + (uint32_t)(lr * LDP + lc) * 2;
        uint32_t bV = sb + AV_VT + (uint32_t)((h * 32 + lr) * LDP + lc) * 2;
        wgemmX<2, 2, 4>(aP, LDP * 2, bV, LDP * 2, ov);
#pragma unroll
        for (int mt = 0; mt < 2; ++mt) {
            int r0 = mrow + mt * 16 + g;
#pragma unroll
            for (int j = 0; j < 4; ++j) {
                int col = h * 32 + j * 8 + t2;
                float* a = ov[mt][j];
                *(__nv_bfloat162*)(xa + r0 * LDB + col)       = __floats2bfloat162_rn(a[0], a[1]);
                *(__nv_bfloat162*)(xa + (r0 + 8) * LDB + col) = __floats2bfloat162_rn(a[2], a[3]);
            }
        }
    }
    __syncthreads();

    {
        const uint4* ws = (const uint4*)(g_wimg + (size_t)3 * IMG);
        uint4* wd = (uint4*)(smraw + AV_WB);
        for (int i = tid; i < 2176; i += TPB) wd[i] = ws[i];
    }
    __syncthreads();
    {
        float fa[1][8][4] = {};
        wgemmX<1, 4, 8>(aEmb, LDB * 2, bW, LDB * 2, fa);
        const int r0 = wrA * 16 + g;
        float rs[2] = {0.f, 0.f}, rq[2] = {0.f, 0.f};
#pragma unroll
        for (int j = 0; j < 8; ++j) {
            int col = wcA * 64 + j * 8 + t2;
            float2 e0 = *(const float2*)(src + r0 * DIM + col);
            float2 e1 = *(const float2*)(src + (r0 + 8) * DIM + col);
            float* a = fa[0][j];
            a[0] += e0.x; a[1] += e0.y; a[2] += e1.x; a[3] += e1.y;
            rs[0] += a[0] + a[1]; rq[0] += a[0] * a[0] + a[1] * a[1];
            rs[1] += a[2] + a[3]; rq[1] += a[2] * a[2] + a[3] * a[3];
        }
#pragma unroll
        for (int i = 0; i < 2; ++i) {
            rs[i] += __shfl_xor_sync(0xffffffffu, rs[i], 1);
            rs[i] += __shfl_xor_sync(0xffffffffu, rs[i], 2);
            rq[i] += __shfl_xor_sync(0xffffffffu, rq[i], 1);
            rq[i] += __shfl_xor_sync(0xffffffffu, rq[i], 2);
        }
        if (t4 == 0) {
            *(float2*)(red + r0 * 4 + wcA * 2)       = make_float2(rs[0], rq[0]);
            *(float2*)(red + (r0 + 8) * 4 + wcA * 2) = make_float2(rs[1], rq[1]);
        }
        __syncthreads();
        float mean[2], rstd[2];
#pragma unroll
        for (int i = 0; i < 2; ++i) {
            int r = r0 + i * 8;
            float s = red[r * 4] + red[r * 4 + 2];
            float q = red[r * 4 + 1] + red[r * 4 + 3];
            float m = s * (1.f / 128.f);
            mean[i] = m;
            rstd[i] = rsqrtf(fmaxf(q * (1.f / 128.f) - m * m, 0.f) + 1e-5f);
        }
        float* og = g_res_inter + (size_t)b * SEQ * DIM;
#pragma unroll
        for (int j = 0; j < 8; ++j) {
            int col = wcA * 64 + j * 8 + t2;
            float2 gm = *(const float2*)(lng + col);
            float2 bt = *(const float2*)(lnb + col);
            float* a = fa[0][j];
            *(float2*)(og + r0 * DIM + col) =
                make_float2((a[0] - mean[0]) * rstd[0] * gm.x + bt.x,
                            (a[1] - mean[0]) * rstd[0] * gm.y + bt.y);
            *(float2*)(og + (r0 + 8) * DIM + col) =
                make_float2((a[2] - mean[1]) * rstd[1] * gm.x + bt.x,
                            (a[3] - mean[1]) * rstd[1] * gm.y + bt.y);
        }
    }
}

// ===========================================================================
// Kernel C v2: FFN + LN via HMMA, 512 threads, 4x4 warp grid (32x32/warp)
// ===========================================================================
#define C_HB   34816
#define C_WB   69632
#define C_XF   104448
#define C_SGB  172032
#define C_RED  173056
#define C_TOT  177152

__global__ void __launch_bounds__(TPBC, 1) kernel_nb_ffn_tc(
    const float* __restrict__ gam, const float* __restrict__ bet,
    float* __restrict__ out) {
    extern __shared__ char smraw[];
    __nv_bfloat16* xa = (__nv_bfloat16*)smraw;
    __nv_bfloat16* hb = (__nv_bfloat16*)(smraw + C_HB);
    __nv_bfloat16* wb = (__nv_bfloat16*)(smraw + C_WB);
    float* xf     = (float*)(smraw + C_XF);
    float* sgam   = (float*)(smraw + C_SGB);
    float* sbet   = sgam + 128;
    float* rowred = (float*)(smraw + C_RED);

    const int tid = threadIdx.x;
    const int w = tid >> 5, lane = tid & 31;
    const int g = lane >> 2, t2 = (lane & 3) * 2;
    const int wr = w >> 2, wc = w & 3;     // 4x4 warp grid over 128x128
    const int lr = lane & 15, lc = (lane >> 4) * 8;
    const uint32_t sb = smem_u32(smraw);
    const uint32_t xaA = sb + (uint32_t)((wr * 32 + lr) * LDB + lc) * 2;
    const uint32_t hbA = sb + C_HB + (uint32_t)((wr * 32 + lr) * LDB + lc) * 2;
    const uint32_t wbA = sb + C_WB + (uint32_t)((wc * 32 + lr) * LDB + lc) * 2;

    const float* xg = g_res_inter + (size_t)blockIdx.x * 128 * DIM;
    for (int i = tid; i < 128 * 32; i += TPBC) {
        int r = i >> 5, c4 = (i & 31) * 4;
        float4 v = *(const float4*)(xg + r * DIM + c4);
        *(float4*)(xf + r * LDX + c4) = v;
        *(__nv_bfloat162*)(xa + r * LDB + c4)     = __floats2bfloat162_rn(v.x, v.y);
        *(__nv_bfloat162*)(xa + r * LDB + c4 + 2) = __floats2bfloat162_rn(v.z, v.w);
    }
    if (tid < 128) { sgam[tid] = gam[tid]; sbet[tid] = bet[tid]; }

    float oacc[2][4][4] = {};
#pragma unroll 1
    for (int c = 0; c < 4; ++c) {
        __syncthreads();
        {
            const uint4* ws = (const uint4*)(g_wimg + (size_t)(4 + c) * IMG);
            uint4* wd = (uint4*)wb;
            for (int i = tid; i < 2176; i += TPBC) wd[i] = ws[i];
        }
        __syncthreads();
        float hacc[2][4][4] = {};
        wgemmX<2, 2, 8>(xaA, LDB * 2, wbA, LDB * 2, hacc);
#pragma unroll
        for (int mt = 0; mt < 2; ++mt) {
            int r0 = wr * 32 + mt * 16 + g;
#pragma unroll
            for (int j = 0; j < 4; ++j) {
                int col = wc * 32 + j * 8 + t2;
                float* a = hacc[mt][j];
                *(__nv_bfloat162*)(hb + r0 * LDB + col) =
                    __floats2bfloat162_rn(fmaxf(a[0], 0.f), fmaxf(a[1], 0.f));
                *(__nv_bfloat162*)(hb + (r0 + 8) * LDB + col) =
                    __floats2bfloat162_rn(fmaxf(a[2], 0.f), fmaxf(a[3], 0.f));
            }
        }
        __syncthreads();
        {
            const uint4* ws = (const uint4*)(g_wimg + (size_t)(8 + c) * IMG);
            uint4* wd = (uint4*)wb;
            for (int i = tid; i < 2176; i += TPBC) wd[i] = ws[i];
        }
        __syncthreads();
        wgemmX<2, 2, 8>(hbA, LDB * 2, wbA, LDB * 2, oacc);
    }
    __syncthreads();

    float rsum[4] = {0.f, 0.f, 0.f, 0.f}, rsq[4] = {0.f, 0.f, 0.f, 0.f};
#pragma unroll
    for (int mt = 0; mt < 2; ++mt) {
        int r0 = wr * 32 + mt * 16 + g;
#pragma unroll
        for (int j = 0; j < 4; ++j) {
            int col = wc * 32 + j * 8 + t2;
            float2 x0 = *(float2*)(xf + r0 * LDX + col);
            float2 x1 = *(float2*)(xf + (r0 + 8) * LDX + col);
            float* a = oacc[mt][j];
            a[0] += x0.x; a[1] += x0.y; a[2] += x1.x; a[3] += x1.y;
            rsum[mt * 2]     += a[0] + a[1];
            rsq[mt * 2]      += a[0] * a[0] + a[1] * a[1];
            rsum[mt * 2 + 1] += a[2] + a[3];
            rsq[mt * 2 + 1]  += a[2] * a[2] + a[3] * a[3];
        }
    }
#pragma unroll
    for (int i = 0; i < 4; ++i) {
        rsum[i] += __shfl_xor_sync(0xffffffffu, rsum[i], 1);
        rsum[i] += __shfl_xor_sync(0xffffffffu, rsum[i], 2);
        rsq[i]  += __shfl_xor_sync(0xffffffffu, rsq[i], 1);
        rsq[i]  += __shfl_xor_sync(0xffffffffu, rsq[i], 2);
    }
    if ((lane & 3) == 0) {
#pragma unroll
        for (int i = 0; i < 4; ++i) {
            int row = wr * 32 + (i >> 1) * 16 + (i & 1) * 8 + g;
            *(float2*)(rowred + row * 8 + wc * 2) = make_float2(rsum[i], rsq[i]);
        }
    }
    __syncthreads();
    float mean[4], rstd[4];
#pragma unroll
    for (int i = 0; i < 4; ++i) {
        int row = wr * 32 + (i >> 1) * 16 + (i & 1) * 8 + g;
        float s = rowred[row * 8] + rowred[row * 8 + 2] + rowred[row * 8 + 4] + rowred[row * 8 + 6];
        float q = rowred[row * 8 + 1] + rowred[row * 8 + 3] + rowred[row * 8 + 5] + rowred[row * 8 + 7];
        float m = s * (1.f / 128.f);
        mean[i] = m;
        rstd[i] = rsqrtf(fmaxf(q * (1.f / 128.f) - m * m, 0.f) + 1e-5f);
    }
    float* og = out + (size_t)blockIdx.x * 128 * DIM;
#pragma unroll
    for (int mt = 0; mt < 2; ++mt) {
        int r0 = wr * 32 + mt * 16 + g;
#pragma unroll
        for (int j = 0; j < 4; ++j) {
            int col = wc * 32 + j * 8 + t2;
            float* a = oacc[mt][j];
            float m0 = mean[mt * 2], s0 = rstd[mt * 2];
            float m1 = mean[mt * 2 + 1], s1 = rstd[mt * 2 + 1];
            *(float2*)(og + r0 * DIM + col) =
                make_float2((a[0] - m0) * s0 * sgam[col] + sbet[col],
                            (a[1] - m0) * s0 * sgam[col + 1] + sbet[col + 1]);
            *(float2*)(og + (r0 + 8) * DIM + col) =
                make_float2((a[2] - m1) * s1 * sgam[col] + sbet[col],
                            (a[3] - m1) * s1 * sgam[col + 1] + sbet[col + 1]);
        }
    }
}

// ===========================================================================
// Scalar machinery for kernel B (unchanged)
// ===========================================================================
template <int K>
__device__ __forceinline__ void gemm_tile(const float* __restrict__ A, int lda,
                                          const float* __restrict__ B, int ldb,
                                          int rg, int cg, float acc[4][8]) {
    const int r0 = rg * 4, c0 = cg * 8;
    const float* Ar = A + r0 * lda;
    const float* Bp = B + c0;
#pragma unroll 4
    for (int k = 0; k < K; ++k) {
        float a0 = Ar[k];
        float a1 = Ar[lda + k];
        float a2 = Ar[2 * lda + k];
        float a3 = Ar[3 * lda + k];
        float4 b0 = *(const float4*)(Bp);
        float4 b1 = *(const float4*)(Bp + 4);
        Bp += ldb;
        float bb[8] = {b0.x, b0.y, b0.z, b0.w, b1.x, b1.y, b1.z, b1.w};
#pragma unroll
        for (int j = 0; j < 8; ++j) {
            acc[0][j] = fmaf(a0, bb[j], acc[0][j]);
            acc[1][j] = fmaf(a1, bb[j], acc[1][j]);
            acc[2][j] = fmaf(a2, bb[j], acc[2][j]);
            acc[3][j] = fmaf(a3, bb[j], acc[3][j]);
        }
    }
}

__device__ __forceinline__ void store_tile(float acc[4][8], float* dst, int rg, int cg) {
#pragma unroll
    for (int i = 0; i < 4; ++i)
#pragma unroll
        for (int j = 0; j < 8; ++j)
            dst[(rg * 4 + i) * LDT + cg * 8 + j] = acc[i][j];
}

__device__ __forceinline__ void load_tile(const float* __restrict__ src, float* dst) {
    for (int i = threadIdx.x; i < 64 * 32; i += TPB) {
        int row = i >> 5, c4 = i & 31;
        *(float4*)(dst + row * LDT + c4 * 4) = *(const float4*)(src + row * 128 + c4 * 4);
    }
}

__device__ __forceinline__ void layernorm_store(const float* __restrict__ buf, int ld,
                                                const float* __restrict__ gam,
                                                const float* __restrict__ bet,
                                                float* __restrict__ out) {
    const int s = threadIdx.x >> 2, q = threadIdx.x & 3;
    const float* row = buf + s * ld;
    float sum = 0.f;
#pragma unroll
    for (int j = 0; j < 32; ++j) sum += row[q * 32 + j];
    sum += __shfl_xor_sync(0xffffffffu, sum, 1);
    sum += __shfl_xor_sync(0xffffffffu, sum, 2);
    float mean = sum * (1.f / 128.f);
    float vs = 0.f;
#pragma unroll
    for (int j = 0; j < 32; ++j) { float d = row[q * 32 + j] - mean; vs = fmaf(d, d, vs); }
    vs += __shfl_xor_sync(0xffffffffu, vs, 1);
    vs += __shfl_xor_sync(0xffffffffu, vs, 2);
    float rstd = rsqrtf(vs * (1.f / 128.f) + 1e-5f);
#pragma unroll
    for (int j = 0; j < 32; ++j) {
        int c = q * 32 + j;
        out[s * 128 + c] = (row[c] - mean) * rstd * gam[c] + bet[c];
    }
}

__device__ __forceinline__ void ffn_ln_store(const float* __restrict__ x_s,
                                             float* __restrict__ h_s,
                                             const float* __restrict__ W1,
                                             const float* __restrict__ W2,
                                             const float* __restrict__ gam,
                                             const float* __restrict__ bet,
                                             float* __restrict__ out,
                                             int rg, int cg) {
    float o[4][8] = {};
#pragma unroll 1
    for (int ch = 0; ch < 4; ++ch) {
        float ha[4][8] = {};
        gemm_tile<128>(x_s, LDT, W1 + ch * 128, DFF, rg, cg, ha);
#pragma unroll
        for (int i = 0; i < 4; ++i)
#pragma unroll
            for (int j = 0; j < 8; ++j)
                h_s[(rg * 4 + i) * LDT + cg * 8 + j] = fmaxf(ha[i][j], 0.f);
        __syncthreads();
        gemm_tile<128>(h_s, LDT, W2 + (size_t)ch * 128 * 128, 128, rg, cg, o);
        __syncthreads();
    }
#pragma unroll
    for (int i = 0; i < 4; ++i)
#pragma unroll
        for (int j = 0; j < 8; ++j) {
            int idx = (rg * 4 + i) * LDT + cg * 8 + j;
            h_s[idx] = o[i][j] + x_s[idx];
        }
    __syncthreads();
    layernorm_store(h_s, LDT, gam, bet, out);
}

// ---------------------------------------------------------------------------
// Kernel B: per-agent self path (scalar, unchanged)
// ---------------------------------------------------------------------------
__global__ void __launch_bounds__(TPB) kernel_self(
    const float* __restrict__ xemb, const float* __restrict__ af,
    const float* __restrict__ WSI, const float* __restrict__ W1,
    const float* __restrict__ W2, const float* __restrict__ gam,
    const float* __restrict__ bet, float* __restrict__ out) {
    extern __shared__ float sm[];
    float* x_s  = sm;
    float* t_s  = sm + 8448;
    float* x1_s = sm + 2 * 8448;
    float* h_s  = sm + 3 * 8448;
    float* a_h  = sm + 4 * 8448;
    const int nAg = blockIdx.x;
    const int tid = threadIdx.x;
    const int rg = tid >> 4, cg = tid & 15;
    const int s = tid >> 2, q4 = tid & 3;

    load_tile(xemb + (size_t)nAg * SEQ * DIM, x_s);
    __syncthreads();

    float val[16] = {};
#pragma unroll 1
    for (int kc = 0; kc < 4; ++kc) {
        float qreg[32];
        const float* qrow = x_s + s * LDT + kc * 32;
#pragma unroll
        for (int kk = 0; kk < 32; ++kk) qreg[kk] = qrow[kk];
#pragma unroll
        for (int j = 0; j < 16; ++j) {
            int t = j * 4 + q4;
            const float* kr = x_s + t * LDT + kc * 32;
            float a = val[j];
#pragma unroll
            for (int kk = 0; kk < 32; ++kk) a = fmaf(qreg[kk], kr[kk], a);
            val[j] = a;
        }
    }
    const float isd = 0.08838834764831845f;
    float mx = val[0] * isd;
#pragma unroll
    for (int j = 0; j < 16; ++j) { val[j] *= isd; mx = fmaxf(mx, val[j]); }
    mx = fmaxf(mx, __shfl_xor_sync(0xffffffffu, mx, 1));
    mx = fmaxf(mx, __shfl_xor_sync(0xffffffffu, mx, 2));
    float ssum = 0.f;
#pragma unroll
    for (int j = 0; j < 16; ++j) { val[j] = expf(val[j] - mx); ssum += val[j]; }
    ssum += __shfl_xor_sync(0xffffffffu, ssum, 1);
    ssum += __shfl_xor_sync(0xffffffffu, ssum, 2);
    float inv = 1.f / ssum;
#pragma unroll
    for (int j = 0; j < 16; ++j) val[j] *= inv;

    const float fct = af[0] * (1.f / NNB);
    float accx[4][8] = {};
#pragma unroll 1
    for (int h = 0; h < NH; ++h) {
        const float* arow = g_att_sum + (((size_t)nAg * NH + h) * SEQ + s) * SEQ;
#pragma unroll
        for (int j = 0; j < 16; ++j) {
            int t = j * 4 + q4;
            a_h[s * LDA + t] = val[j] + fct * arow[t];
        }
        __syncthreads();
        float ta[4][8] = {};
        gemm_tile<64>(a_h, LDA, x_s, LDT, rg, cg, ta);
        store_tile(ta, t_s, rg, cg);
        __syncthreads();
        gemm_tile<128>(t_s, LDT, WSI + (size_t)h * 128 * 128, 128, rg, cg, accx);
        __syncthreads();
    }
    store_tile(accx, x1_s, rg, cg);
    __syncthreads();
    ffn_ln_store(x1_s, h_s, W1, W2, gam, bet, out + (size_t)nAg * SEQ * DIM, rg, cg);
}

// ---------------------------------------------------------------------------
extern "C" void kernel_launch(void* const* d_in, const int* in_sizes, int n_in,
                              void* d_out, int out_size) {
    const float* x_emb  = (const float*)d_in[0];
    const float* nb_emb = (const float*)d_in[1];
    const void*  mask   = d_in[2];
    const float* att_f  = (const float*)d_in[3];
    const float* WQ     = (const float*)d_in[4];
    const float* WK     = (const float*)d_in[5];
    const float* WV     = (const float*)d_in[6];
    const float* Wfc    = (const float*)d_in[7];
    const float* ln_mg  = (const float*)d_in[8];
    const float* ln_mb  = (const float*)d_in[9];
    const float* WSI    = (const float*)d_in[10];
    const float* W1s    = (const float*)d_in[11];
    const float* W2s    = (const float*)d_in[12];
    const float* ln_sg  = (const float*)d_in[13];
    const float* ln_sb  = (const float*)d_in[14];
    const float* W1i    = (const float*)d_in[15];
    const float* W2i    = (const float*)d_in[16];
    const float* ln_ig  = (const float*)d_in[17];
    const float* ln_ib  = (const float*)d_in[18];
    float* out_x  = (float*)d_out;
    float* out_nb = out_x + (size_t)NAG * SEQ * DIM;

    void* att_ptr = nullptr;
    cudaGetSymbolAddress(&att_ptr, g_att_sum);
    cudaMemsetAsync(att_ptr, 0, sizeof(float) * (size_t)NAG * NH * SEQ * SEQ, 0);
    void* flag_ptr = nullptr;
    cudaGetSymbolAddress(&flag_ptr, g_mask_is_bytes);
    cudaMemsetAsync(flag_ptr, 0, sizeof(int), 0);
    detect_mask_kernel<<<256, 256>>>((const unsigned int*)mask);
    prep_weights_kernel<<<192, 256>>>(WQ, WK, WV, Wfc, W1i, W2i);

    const size_t smB = sizeof(float) * (4 * 8448 + 64 * LDA);
    cudaFuncSetAttribute(kernel_mha,       cudaFuncAttributeMaxDynamicSharedMemorySize, AV_TOT);
    cudaFuncSetAttribute(kernel_self,      cudaFuncAttributeMaxDynamicSharedMemorySize, (int)smB);
    cudaFuncSetAttribute(kernel_nb_ffn_tc, cudaFuncAttributeMaxDynamicSharedMemorySize, C_TOT);

    kernel_mha<<<NAG * NNB, TPB, AV_TOT>>>(nb_emb, mask, ln_mg, ln_mb);

    // Fork: B on side stream, C on main stream, then join.
    cudaEventRecord(g_si.evA, 0);
    cudaStreamWaitEvent(g_si.s, g_si.evA, 0);
    kernel_self<<<NAG, TPB, smB, g_si.s>>>(x_emb, att_f, WSI, W1s, W2s, ln_sg, ln_sb, out_x);
    cudaEventRecord(g_si.evB, g_si.s);
    kernel_nb_ffn_tc<<<NAG * NNB / 2, TPBC, C_TOT>>>(ln_ig, ln_ib, out_nb);
    cudaStreamWaitEvent(0, g_si.evB, 0);
}